// round 11
// baseline (speedup 1.0000x reference)
#include <cuda_runtime.h>
#include <cuda_fp16.h>
#include <stdint.h>
#include <math.h>

#define BB    2048
#define REPRK 8192
#define SS    24
#define DD    8
#define SBH   384   // S*BINS

// ===================== PTX helpers (non-arch-specific) ======================
__device__ __forceinline__ uint32_t smem_u32(const void* p) {
    uint32_t a;
    asm("{ .reg .u64 t; cvta.to.shared.u64 t, %1; cvt.u32.u64 %0, t; }" : "=r"(a) : "l"(p));
    return a;
}
__device__ __forceinline__ void cp16(uint32_t saddr, const void* g) {
    asm volatile("cp.async.cg.shared.global [%0], [%1], 16;" :: "r"(saddr), "l"(g));
}
#define CPCOMMIT asm volatile("cp.async.commit_group;" ::: "memory")
#define CPWAIT1  asm volatile("cp.async.wait_group 1;" ::: "memory")

__device__ __forceinline__ void ldsm4(uint32_t* r, uint32_t addr) {
    asm volatile("ldmatrix.sync.aligned.m8n8.x4.shared.b16 {%0,%1,%2,%3}, [%4];"
        : "=r"(r[0]), "=r"(r[1]), "=r"(r[2]), "=r"(r[3]) : "r"(addr));
}
// fp16 inputs, f32 accumulator
__device__ __forceinline__ void mma_f32acc(float* d, const uint32_t* a, uint32_t b0, uint32_t b1) {
    asm volatile("mma.sync.aligned.m16n8k16.row.col.f32.f16.f16.f32 "
        "{%0,%1,%2,%3}, {%4,%5,%6,%7}, {%8,%9}, {%0,%1,%2,%3};"
        : "+f"(d[0]), "+f"(d[1]), "+f"(d[2]), "+f"(d[3])
        : "r"(a[0]), "r"(a[1]), "r"(a[2]), "r"(a[3]), "r"(b0), "r"(b1));
}

// ===================== scratch (device globals) =============================
__device__ __half g_Ahi[(size_t)BB * REPRK];       // 32 MB
__device__ __half g_WrgbTh[(size_t)512 * REPRK];   // 8 MB
__device__ float g_rgb_part[4 * BB * 512];         // 16 MB: rgb splitk, then t0p/qbp
__device__ __half g_xvh[BB * 512];
__device__ __half g_xqh[BB * 512];
__device__ __half g_vW1Th[512 * 512];
__device__ __half g_vW2Th[512 * 512];
__device__ __half g_qW1Th[512 * 512];
__device__ __half g_qW2Th[512 * 512];
__device__ __half g_t1h[BB * 512];
__device__ float g_act[BB * SS * DD];
__device__ __half g_q1h[(size_t)BB * SS * 512];    // 50 MB (s-major rows)
__device__ float g_q2pre[(size_t)BB * SS * 512];   // 100 MB (s-major rows)

// ===================== small helpers ========================================
__device__ __forceinline__ float silu(float z) { return z / (1.f + expf(-z)); }

__device__ __forceinline__ float2 blockReduce2_256(float2 v) {
    __shared__ float2 sm[8];
    int lane = threadIdx.x & 31, w = threadIdx.x >> 5;
    #pragma unroll
    for (int o = 16; o > 0; o >>= 1) {
        v.x += __shfl_xor_sync(0xffffffffu, v.x, o);
        v.y += __shfl_xor_sync(0xffffffffu, v.y, o);
    }
    if (lane == 0) sm[w] = v;
    __syncthreads();
    if (threadIdx.x == 0) {
        float2 t = sm[0];
        #pragma unroll
        for (int i = 1; i < 8; i++) { t.x += sm[i].x; t.y += sm[i].y; }
        sm[0] = t;
    }
    __syncthreads();
    float2 r = sm[0];
    __syncthreads();
    return r;
}

// ===================== HMMA single-pass fp16 GEMM core (128x128 tile) =======
// C = A * B^T over K range [kbase, kbase + nch*32). A[M][lda], B[N][lda] fp16.
__device__ __forceinline__ void gemm_core(
    const __half* __restrict__ A, const __half* __restrict__ B,
    float* __restrict__ C, int m0, int n0, int kbase, int lda, int N, int nch,
    char* smdyn) {
    const int tid = threadIdx.x;
    const int lane = tid & 31, wid = tid >> 5;
    const int wm = wid & 3, wn = wid >> 2;

    const int lrow = tid >> 2, lc = tid & 3;
    const int lpc = lc ^ ((lrow >> 1) & 3);
    const uint32_t sb0 = smem_u32(smdyn);
    const uint32_t s_store = sb0 + lrow * 64 + lpc * 16;
    const __half* gA = A + (size_t)(m0 + lrow) * lda + kbase + lc * 8;
    const __half* gB = B + (size_t)(n0 + lrow) * lda + kbase + lc * 8;

#define LOADST(s, i) do { \
    uint32_t _so = s_store + (uint32_t)(s) * 16384u; \
    size_t _ko = (size_t)(i) * 32; \
    cp16(_so,        gA + _ko); \
    cp16(_so + 8192, gB + _ko); } while (0)

    LOADST(0, 0); CPCOMMIT;
    LOADST(1, 1); CPCOMMIT;

    float acc[2][4][4];
    #pragma unroll
    for (int mf = 0; mf < 2; mf++)
        #pragma unroll
        for (int nf = 0; nf < 4; nf++)
            #pragma unroll
            for (int r = 0; r < 4; r++) acc[mf][nf][r] = 0.f;

    const int r15 = lane & 15, ksel = lane >> 4;

    for (int i = 0; i < nch; i++) {
        CPWAIT1;
        __syncthreads();
        uint32_t sb = sb0 + (uint32_t)(i & 1) * 16384u;
        #pragma unroll
        for (int kt = 0; kt < 2; kt++) {
            const int cA = 2 * kt + ksel;
            uint32_t a[2][4], b[2][4];
            #pragma unroll
            for (int mf = 0; mf < 2; mf++) {
                int row = wm * 32 + mf * 16 + r15;
                uint32_t off = (uint32_t)(row * 64 + ((cA ^ ((row >> 1) & 3)) * 16));
                ldsm4(a[mf], sb + off);
            }
            #pragma unroll
            for (int nf2 = 0; nf2 < 2; nf2++) {
                int row = wn * 32 + nf2 * 16 + r15;
                uint32_t off = (uint32_t)(row * 64 + ((cA ^ ((row >> 1) & 3)) * 16));
                ldsm4(b[nf2], sb + 8192 + off);
            }
            #pragma unroll
            for (int mf = 0; mf < 2; mf++)
                #pragma unroll
                for (int nf = 0; nf < 4; nf++)
                    mma_f32acc(acc[mf][nf], a[mf], b[nf >> 1][nf & 1], b[nf >> 1][2 + (nf & 1)]);
        }
        __syncthreads();
        if (i + 2 < nch) LOADST(i & 1, i + 2);
        CPCOMMIT;
    }
#undef LOADST

    #pragma unroll
    for (int mf = 0; mf < 2; mf++)
        #pragma unroll
        for (int nf = 0; nf < 4; nf++) {
            int m = m0 + wm * 32 + mf * 16 + (lane >> 2);
            int n = n0 + wn * 32 + nf * 8 + (lane & 3) * 2;
            *(float2*)&C[(size_t)m * N + n] = make_float2(acc[mf][nf][0], acc[mf][nf][1]);
            *(float2*)&C[(size_t)(m + 8) * N + n] = make_float2(acc[mf][nf][2], acc[mf][nf][3]);
        }
}

// rgb GEMM: grid (4, 16, 4) splitk over K=8192
__global__ __launch_bounds__(512, 1)
void gemm_rgb(const __half* __restrict__ A, const __half* __restrict__ B,
              float* __restrict__ C) {
    extern __shared__ char smdyn[];
    gemm_core(A, B, C + (size_t)blockIdx.z * BB * 512,
              blockIdx.y * 128, blockIdx.x * 128, blockIdx.z * 2048, REPRK, 512, 64, smdyn);
}

// vW1 + qW1 packed, each splitk2. grid (4, 16, 4): z = job*2 + kz
__global__ __launch_bounds__(512, 1)
void gemm_dualA(const __half* __restrict__ xvh, const __half* __restrict__ vB,
                const __half* __restrict__ xqh, const __half* __restrict__ qB,
                float* __restrict__ t0p, float* __restrict__ qbp) {
    extern __shared__ char smdyn[];
    int job = blockIdx.z >> 1, kz = blockIdx.z & 1;
    const __half* A = job ? xqh : xvh;
    const __half* B = job ? qB : vB;
    float* C = (job ? qbp : t0p) + (size_t)kz * BB * 512;
    gemm_core(A, B, C, blockIdx.y * 128, blockIdx.x * 128, kz * 256, 512, 512, 8, smdyn);
}

// qW2 (full) + vW2 (splitk2) packed. grid (4, 416)
__global__ __launch_bounds__(512, 1)
void gemm_dualB(const __half* __restrict__ q1h, const __half* __restrict__ qB,
                const __half* __restrict__ t1h, const __half* __restrict__ vB,
                float* __restrict__ q2pre, float* __restrict__ t0p) {
    extern __shared__ char smdyn[];
    int y = blockIdx.y;
    if (y < 384) {
        gemm_core(q1h, qB, q2pre, y * 128, blockIdx.x * 128, 0, 512, 512, 16, smdyn);
    } else {
        int j = y - 384, kz = j >> 4, y2 = j & 15;
        gemm_core(t1h, vB, t0p + (size_t)kz * BB * 512,
                  y2 * 128, blockIdx.x * 128, kz * 256, 512, 512, 8, smdyn);
    }
}

// ===================== prep kernels =========================================
// rgb_obs f32 -> fp16
__global__ void conv_hi(const float* __restrict__ x, __half* __restrict__ h, int n4) {
    int i = blockIdx.x * blockDim.x + threadIdx.x;
    if (i >= n4) return;
    float4 v = ((const float4*)x)[i];
    ((__half2*)h)[i * 2]     = __halves2half2(__float2half_rn(v.x), __float2half_rn(v.y));
    ((__half2*)h)[i * 2 + 1] = __halves2half2(__float2half_rn(v.z), __float2half_rn(v.w));
}

// all four 512x512 weight transposes (f32 -> fp16) in one launch
__global__ void trans4(const float* __restrict__ W0, __half* __restrict__ T0,
                       const float* __restrict__ W1, __half* __restrict__ T1,
                       const float* __restrict__ W2, __half* __restrict__ T2,
                       const float* __restrict__ W3, __half* __restrict__ T3) {
    __shared__ float t[32][33];
    int z = blockIdx.z;
    const float* W = z == 0 ? W0 : z == 1 ? W1 : z == 2 ? W2 : W3;
    __half* T = z == 0 ? T0 : z == 1 ? T1 : z == 2 ? T2 : T3;
    int k0 = blockIdx.x * 32, n0 = blockIdx.y * 32;
    int tx = threadIdx.x, ty = threadIdx.y;
    #pragma unroll
    for (int i = 0; i < 4; i++)
        t[ty + i * 8][tx] = W[(size_t)(k0 + ty + i * 8) * 512 + n0 + tx];
    __syncthreads();
    #pragma unroll
    for (int i = 0; i < 4; i++)
        T[(size_t)(n0 + ty + i * 8) * 512 + k0 + tx] = __float2half_rn(t[tx][ty + i * 8]);
}

__global__ void trans_rgb(const float* __restrict__ vW, const float* __restrict__ qW,
                          __half* __restrict__ T) {
    __shared__ float t[32][33];
    int k0 = blockIdx.x * 32, n0 = blockIdx.y * 32;
    int tx = threadIdx.x, ty = threadIdx.y;
    const float* src = (n0 < 256) ? vW : qW;
    int nb = (n0 < 256) ? n0 : (n0 - 256);
    #pragma unroll
    for (int i = 0; i < 4; i++)
        t[ty + i * 8][tx] = src[(size_t)(k0 + ty + i * 8) * 256 + nb + tx];
    __syncthreads();
    #pragma unroll
    for (int i = 0; i < 4; i++)
        T[(size_t)(n0 + ty + i * 8) * REPRK + k0 + tx] = __float2half_rn(t[tx][ty + i * 8]);
}

// ===================== activation kernels ===================================
__global__ void ln_tanh_rgb(const float* __restrict__ part,
                            const float* __restrict__ vg, const float* __restrict__ vb,
                            const float* __restrict__ qg, const float* __restrict__ qb,
                            __half* __restrict__ xvh, __half* __restrict__ xqh) {
    int b = blockIdx.x, hsel = blockIdx.y, j = threadIdx.x;
    const size_t np = (size_t)BB * 512;
    size_t off = (size_t)b * 512 + hsel * 256 + j;
    float x = part[off] + part[off + np] + part[off + 2 * np] + part[off + 3 * np];
    float2 r = blockReduce2_256(make_float2(x, x * x));
    float mu = r.x * (1.f / 256.f);
    float inv = rsqrtf(r.y * (1.f / 256.f) - mu * mu + 1e-5f);
    const float* g  = hsel ? qg : vg;
    const float* be = hsel ? qb : vb;
    float y = tanhf((x - mu) * inv * g[j] + be[j]);
    __half* dst = hsel ? xqh : xvh;
    dst[(size_t)b * 512 + j] = __float2half_rn(y);
}

__global__ void low_kernel(const float* __restrict__ low,
                           const float* __restrict__ vW, const float* __restrict__ vg, const float* __restrict__ vb,
                           const float* __restrict__ qW, const float* __restrict__ qg, const float* __restrict__ qb,
                           __half* __restrict__ xvh, __half* __restrict__ xqh) {
    int b = blockIdx.x, j = threadIdx.x;
    __shared__ float lo[32];
    if (j < 32) lo[j] = low[b * 32 + j];
    __syncthreads();
    float sv = 0.f, sq = 0.f;
    #pragma unroll 8
    for (int k = 0; k < 32; k++) {
        float l = lo[k];
        sv += l * vW[k * 256 + j];
        sq += l * qW[k * 256 + j];
    }
    float2 rv = blockReduce2_256(make_float2(sv, sv * sv));
    float muv = rv.x * (1.f / 256.f);
    float iv  = rsqrtf(rv.y * (1.f / 256.f) - muv * muv + 1e-5f);
    xvh[(size_t)b * 512 + 256 + j] = __float2half_rn(tanhf((sv - muv) * iv * vg[j] + vb[j]));
    float2 rq = blockReduce2_256(make_float2(sq, sq * sq));
    float muq = rq.x * (1.f / 256.f);
    float iq  = rsqrtf(rq.y * (1.f / 256.f) - muq * muq + 1e-5f);
    xqh[(size_t)b * 512 + 256 + j] = __float2half_rn(tanhf((sq - muq) * iq * qg[j] + qb[j]));
}

// one thread per (b, s): contiguous 32B stores
__global__ void act_kernel(const int* __restrict__ cat, float* __restrict__ act) {
    int t = blockIdx.x * blockDim.x + threadIdx.x;
    if (t >= BB * SS) return;
    int b = t / SS, k = t - b * SS;
    int ls = k >> 3, ds = k & 7;
    float out[8];
    #pragma unroll
    for (int d = 0; d < 8; d++) {
        int lvl = ls + (d < ds ? 1 : 0);
        float lowv = -1.f, width = 2.f, mid = 0.f;
        for (int l = 0; l < lvl; l++) {
            float w = width * (1.f / 16.f);
            float c = (float)cat[(b * 3 + l) * 8 + d];
            float nl = lowv + c * w;
            mid = nl + 0.5f * w;
            lowv = nl; width = w;
        }
        out[d] = (lvl == 0) ? 0.f : mid;
    }
    float4* dst = (float4*)&act[(size_t)t * 8];
    dst[0] = make_float4(out[0], out[1], out[2], out[3]);
    dst[1] = make_float4(out[4], out[5], out[6], out[7]);
}

// blocks [0,2048): q1_all (reads qbp partials); [2048,4096): ln_silu (t0p)
__global__ __launch_bounds__(256)
void mid_k(const float* __restrict__ qbp, const float* __restrict__ act,
           const float* __restrict__ qW1, const float* __restrict__ qg1, const float* __restrict__ qb1,
           const float* __restrict__ t0p, const float* __restrict__ vg1, const float* __restrict__ vb1,
           __half* __restrict__ q1h, __half* __restrict__ t1h) {
    const size_t np = (size_t)BB * 512;
    int j = threadIdx.x;
    if (blockIdx.x < BB) {
        __shared__ float wact[8 * 512];
        __shared__ float as[SS * DD];
        int b = blockIdx.x;
        for (int i = j; i < 8 * 512; i += 256)
            wact[i] = qW1[(size_t)(512 + (i >> 9)) * 512 + (i & 511)];
        for (int i = j; i < SS * DD; i += 256)
            as[i] = act[(size_t)b * SS * DD + i];
        float b0 = qbp[(size_t)b * 512 + j]       + qbp[np + (size_t)b * 512 + j];
        float b1 = qbp[(size_t)b * 512 + 256 + j] + qbp[np + (size_t)b * 512 + 256 + j];
        float g0 = qg1[j], g1 = qg1[j + 256], e0 = qb1[j], e1 = qb1[j + 256];
        __syncthreads();
        for (int s = 0; s < SS; s++) {
            float x0 = b0, x1 = b1;
            #pragma unroll
            for (int d = 0; d < 8; d++) {
                float av = as[s * 8 + d];
                x0 += av * wact[d * 512 + j];
                x1 += av * wact[d * 512 + 256 + j];
            }
            float2 r = blockReduce2_256(make_float2(x0 + x1, x0 * x0 + x1 * x1));
            float mu = r.x * (1.f / 512.f);
            float inv = rsqrtf(r.y * (1.f / 512.f) - mu * mu + 1e-5f);
            size_t row = (size_t)s * BB + b;
            q1h[row * 512 + j]       = __float2half_rn(silu((x0 - mu) * inv * g0 + e0));
            q1h[row * 512 + 256 + j] = __float2half_rn(silu((x1 - mu) * inv * g1 + e1));
        }
    } else {
        size_t row = blockIdx.x - BB;
        float x0 = t0p[row * 512 + j]       + t0p[np + row * 512 + j];
        float x1 = t0p[row * 512 + 256 + j] + t0p[np + row * 512 + 256 + j];
        float2 r = blockReduce2_256(make_float2(x0 + x1, x0 * x0 + x1 * x1));
        float mu = r.x * (1.f / 512.f);
        float inv = rsqrtf(r.y * (1.f / 512.f) - mu * mu + 1e-5f);
        t1h[row * 512 + j]       = __float2half_rn(silu((x0 - mu) * inv * vg1[j] + vb1[j]));
        t1h[row * 512 + 256 + j] = __float2half_rn(silu((x1 - mu) * inv * vg1[j + 256] + vb1[j + 256]));
    }
}

// vW2 partials -> LN -> SiLU -> value head, one block per b
__global__ __launch_bounds__(256)
void vfin(const float* __restrict__ t0p, const float* __restrict__ g,
          const float* __restrict__ be, const float* __restrict__ Wh,
          const float* __restrict__ bh, float* __restrict__ out) {
    const size_t np = (size_t)BB * 512;
    int b = blockIdx.x, j = threadIdx.x;
    float x0 = t0p[(size_t)b * 512 + j]       + t0p[np + (size_t)b * 512 + j];
    float x1 = t0p[(size_t)b * 512 + 256 + j] + t0p[np + (size_t)b * 512 + 256 + j];
    float2 r = blockReduce2_256(make_float2(x0 + x1, x0 * x0 + x1 * x1));
    float mu = r.x * (1.f / 512.f);
    float inv = rsqrtf(r.y * (1.f / 512.f) - mu * mu + 1e-5f);
    float y0 = silu((x0 - mu) * inv * g[j] + be[j]);
    float y1 = silu((x1 - mu) * inv * g[j + 256] + be[j + 256]);
    float s = y0 * Wh[j] + y1 * Wh[256 + j];
    float2 r2 = blockReduce2_256(make_float2(s, 0.f));
    if (j == 0) out[b] = r2.x + bh[0];
}

// ---- fused LN + SiLU + diagonal q-head over q2pre (s-major rows) ----------
#define YSLD 520
__global__ __launch_bounds__(256)
void lnhead_q(const float* __restrict__ pre, const float* __restrict__ g,
              const float* __restrict__ be, const float* __restrict__ Wh,
              const float* __restrict__ bh, float* __restrict__ out) {
    extern __shared__ float sm[];
    float* whs = sm;             // [512][16]
    float* ys  = sm + 512 * 16;  // [64][YSLD]
    const int tid = threadIdx.x, lane = tid & 31, w = tid >> 5;
    const int r0 = blockIdx.x * 64;
    const int s16 = (r0 >> 11) * 16;

    for (int i = tid; i < 512 * 16; i += 256)
        whs[i] = Wh[(size_t)(i >> 4) * SBH + s16 + (i & 15)];

    for (int rr = w; rr < 64; rr += 8) {
        const float* row = pre + (size_t)(r0 + rr) * 512;
        float v[16];
        float s1 = 0.f, s2 = 0.f;
        #pragma unroll
        for (int i = 0; i < 16; i++) {
            v[i] = row[lane + i * 32];
            s1 += v[i]; s2 += v[i] * v[i];
        }
        #pragma unroll
        for (int o = 16; o > 0; o >>= 1) {
            s1 += __shfl_xor_sync(0xffffffffu, s1, o);
            s2 += __shfl_xor_sync(0xffffffffu, s2, o);
        }
        float mu = s1 * (1.f / 512.f);
        float inv = rsqrtf(s2 * (1.f / 512.f) - mu * mu + 1e-5f);
        #pragma unroll
        for (int i = 0; i < 16; i++) {
            int col = lane + i * 32;
            ys[rr * YSLD + col] = silu((v[i] - mu) * inv * g[col] + be[col]);
        }
    }
    __syncthreads();

    const int rid = tid >> 3, c2 = tid & 7;
    const float2 bias = *(const float2*)&bh[s16 + c2 * 2];
    float a0 = 0.f, a1 = 0.f, c0 = 0.f, c1 = 0.f;
    const float* y0r = ys + rid * YSLD;
    const float* y1r = ys + (rid + 32) * YSLD;
    #pragma unroll 8
    for (int k = 0; k < 512; k++) {
        float2 w2 = *(const float2*)&whs[k * 16 + c2 * 2];
        float ya = y0r[k], yb = y1r[k];
        a0 += ya * w2.x; a1 += ya * w2.y;
        c0 += yb * w2.x; c1 += yb * w2.y;
    }
    int brow0 = (r0 + rid) & (BB - 1);
    int brow1 = (r0 + rid + 32) & (BB - 1);
    *(float2*)&out[(size_t)brow0 * SBH + s16 + c2 * 2] = make_float2(a0 + bias.x, a1 + bias.y);
    *(float2*)&out[(size_t)brow1 * SBH + s16 + c2 * 2] = make_float2(c0 + bias.x, c1 + bias.y);
}

// ===================== launch ================================================
#define GEMM_DSMEM 32768
#define LNHEAD_DSMEM ((512 * 16 + 64 * YSLD) * 4)

extern "C" void kernel_launch(void* const* d_in, const int* in_sizes, int n_in,
                              void* d_out, int out_size) {
    const float* rgb_obs = (const float*)d_in[0];
    const float* low_obs = (const float*)d_in[1];
    const int*   category = (const int*)d_in[2];
    const float* v_W_rgb = (const float*)d_in[3];
    const float* v_g_rgb = (const float*)d_in[4];
    const float* v_b_rgb = (const float*)d_in[5];
    const float* v_W_low = (const float*)d_in[6];
    const float* v_g_low = (const float*)d_in[7];
    const float* v_b_low = (const float*)d_in[8];
    const float* v_W1 = (const float*)d_in[9];
    const float* v_g1 = (const float*)d_in[10];
    const float* v_b1 = (const float*)d_in[11];
    const float* v_W2 = (const float*)d_in[12];
    const float* v_g2 = (const float*)d_in[13];
    const float* v_b2 = (const float*)d_in[14];
    const float* v_Wh = (const float*)d_in[15];
    const float* v_bh = (const float*)d_in[16];
    const float* q_W_rgb = (const float*)d_in[17];
    const float* q_g_rgb = (const float*)d_in[18];
    const float* q_b_rgb = (const float*)d_in[19];
    const float* q_W_low = (const float*)d_in[20];
    const float* q_g_low = (const float*)d_in[21];
    const float* q_b_low = (const float*)d_in[22];
    const float* q_W1 = (const float*)d_in[23];
    const float* q_g1 = (const float*)d_in[24];
    const float* q_b1 = (const float*)d_in[25];
    const float* q_W2 = (const float*)d_in[26];
    const float* q_g2 = (const float*)d_in[27];
    const float* q_b2 = (const float*)d_in[28];
    const float* q_Wh = (const float*)d_in[29];
    const float* q_bh = (const float*)d_in[30];

    float* out_value = (float*)d_out;
    float* out_adv   = out_value + BB;

    cudaFuncSetAttribute(gemm_rgb,   cudaFuncAttributeMaxDynamicSharedMemorySize, GEMM_DSMEM);
    cudaFuncSetAttribute(gemm_dualA, cudaFuncAttributeMaxDynamicSharedMemorySize, GEMM_DSMEM);
    cudaFuncSetAttribute(gemm_dualB, cudaFuncAttributeMaxDynamicSharedMemorySize, GEMM_DSMEM);
    cudaFuncSetAttribute(lnhead_q,   cudaFuncAttributeMaxDynamicSharedMemorySize, LNHEAD_DSMEM);

    __half *Ahi, *WrgbT, *xvh, *xqh;
    __half *vW1T, *vW2T, *qW1T, *qW2T;
    __half *t1h, *q1h;
    float *rgb_part, *act, *q2pre;
    cudaGetSymbolAddress((void**)&Ahi, g_Ahi);
    cudaGetSymbolAddress((void**)&WrgbT, g_WrgbTh);
    cudaGetSymbolAddress((void**)&rgb_part, g_rgb_part);
    cudaGetSymbolAddress((void**)&xvh, g_xvh);
    cudaGetSymbolAddress((void**)&xqh, g_xqh);
    cudaGetSymbolAddress((void**)&vW1T, g_vW1Th);
    cudaGetSymbolAddress((void**)&vW2T, g_vW2Th);
    cudaGetSymbolAddress((void**)&qW1T, g_qW1Th);
    cudaGetSymbolAddress((void**)&qW2T, g_qW2Th);
    cudaGetSymbolAddress((void**)&t1h, g_t1h);
    cudaGetSymbolAddress((void**)&act, g_act);
    cudaGetSymbolAddress((void**)&q1h, g_q1h);
    cudaGetSymbolAddress((void**)&q2pre, g_q2pre);

    float* t0p = rgb_part;                        // slices 0,1
    float* qbp = rgb_part + 2 * (size_t)BB * 512; // slices 2,3

    // ---- prep ----
    act_kernel<<<(BB * SS + 255) / 256, 256>>>(category, act);
    conv_hi<<<(BB * REPRK / 4 + 255) / 256, 256>>>(rgb_obs, Ahi, BB * REPRK / 4);
    trans_rgb<<<dim3(REPRK / 32, 512 / 32), dim3(32, 8)>>>(v_W_rgb, q_W_rgb, WrgbT);
    trans4<<<dim3(16, 16, 4), dim3(32, 8)>>>(v_W1, vW1T, v_W2, vW2T, q_W1, qW1T, q_W2, qW2T);

    // ---- shared rgb features: split-K=4 over K=8192, reduce folded into LN ----
    gemm_rgb<<<dim3(4, BB / 128, 4), 512, GEMM_DSMEM>>>(Ahi, WrgbT, rgb_part);
    ln_tanh_rgb<<<dim3(BB, 2), 256>>>(rgb_part, v_g_rgb, v_b_rgb, q_g_rgb, q_b_rgb, xvh, xqh);
    low_kernel<<<BB, 256>>>(low_obs, v_W_low, v_g_low, v_b_low, q_W_low, q_g_low, q_b_low,
                            xvh, xqh);

    // ---- layer 1 (v + q packed, split-K=2 each) ----
    gemm_dualA<<<dim3(4, 16, 4), 512, GEMM_DSMEM>>>(xvh, vW1T, xqh, qW1T, t0p, qbp);
    // ---- q1 expansion + v ln_silu in one launch ----
    mid_k<<<2 * BB, 256>>>(qbp, act, q_W1, q_g1, q_b1, t0p, v_g1, v_b1, q1h, t1h);

    // ---- layer 2: qW2 (big) + vW2 (splitk2) packed ----
    gemm_dualB<<<dim3(4, 416), 512, GEMM_DSMEM>>>(q1h, qW2T, t1h, vW2T, q2pre, t0p);

    // ---- heads ----
    vfin<<<BB, 256>>>(t0p, v_g2, v_b2, v_Wh, v_bh, out_value);
    lnhead_q<<<(BB * SS) / 64, 256, LNHEAD_DSMEM>>>(q2pre, q_g2, q_b2, q_Wh, q_bh, out_adv);
}

// round 12
// speedup vs baseline: 1.5670x; 1.5670x over previous
#include <cuda_runtime.h>
#include <cuda_fp16.h>
#include <stdint.h>
#include <math.h>

#define BB    2048
#define REPRK 8192
#define SS    24
#define DD    8
#define SBH   384   // S*BINS

// ===================== PTX helpers (non-arch-specific) ======================
__device__ __forceinline__ uint32_t smem_u32(const void* p) {
    uint32_t a;
    asm("{ .reg .u64 t; cvta.to.shared.u64 t, %1; cvt.u32.u64 %0, t; }" : "=r"(a) : "l"(p));
    return a;
}
__device__ __forceinline__ void cp16(uint32_t saddr, const void* g) {
    asm volatile("cp.async.cg.shared.global [%0], [%1], 16;" :: "r"(saddr), "l"(g));
}
#define CPCOMMIT asm volatile("cp.async.commit_group;" ::: "memory")
#define CPWAIT2  asm volatile("cp.async.wait_group 2;" ::: "memory")

__device__ __forceinline__ void ldsm4(uint32_t* r, uint32_t addr) {
    asm volatile("ldmatrix.sync.aligned.m8n8.x4.shared.b16 {%0,%1,%2,%3}, [%4];"
        : "=r"(r[0]), "=r"(r[1]), "=r"(r[2]), "=r"(r[3]) : "r"(addr));
}
// fp16 inputs, f32 accumulator
__device__ __forceinline__ void mma_f32acc(float* d, const uint32_t* a, uint32_t b0, uint32_t b1) {
    asm volatile("mma.sync.aligned.m16n8k16.row.col.f32.f16.f16.f32 "
        "{%0,%1,%2,%3}, {%4,%5,%6,%7}, {%8,%9}, {%0,%1,%2,%3};"
        : "+f"(d[0]), "+f"(d[1]), "+f"(d[2]), "+f"(d[3])
        : "r"(a[0]), "r"(a[1]), "r"(a[2]), "r"(a[3]), "r"(b0), "r"(b1));
}

// ===================== scratch (device globals) =============================
__device__ __half g_Ahi[(size_t)BB * REPRK];       // 32 MB
__device__ __half g_WrgbTh[(size_t)512 * REPRK];   // 8 MB
__device__ float g_rgb_part[4 * BB * 512];         // 16 MB: rgb splitk, then t0p/qbp
__device__ __half g_xvh[BB * 512];
__device__ __half g_xqh[BB * 512];
__device__ __half g_vW1Th[512 * 512];
__device__ __half g_vW2Th[512 * 512];
__device__ __half g_qW1Th[512 * 512];
__device__ __half g_qW2Th[512 * 512];
__device__ __half g_t1h[BB * 512];
__device__ float g_act[BB * SS * DD];
__device__ __half g_q1h[(size_t)BB * SS * 512];    // 50 MB (s-major rows)
__device__ float g_q2pre[(size_t)BB * SS * 512];   // 100 MB (s-major rows)

// ===================== small helpers ========================================
__device__ __forceinline__ float silu(float z) { return z / (1.f + expf(-z)); }

__device__ __forceinline__ float2 blockReduce2_256(float2 v) {
    __shared__ float2 sm[8];
    int lane = threadIdx.x & 31, w = threadIdx.x >> 5;
    #pragma unroll
    for (int o = 16; o > 0; o >>= 1) {
        v.x += __shfl_xor_sync(0xffffffffu, v.x, o);
        v.y += __shfl_xor_sync(0xffffffffu, v.y, o);
    }
    if (lane == 0) sm[w] = v;
    __syncthreads();
    if (threadIdx.x == 0) {
        float2 t = sm[0];
        #pragma unroll
        for (int i = 1; i < 8; i++) { t.x += sm[i].x; t.y += sm[i].y; }
        sm[0] = t;
    }
    __syncthreads();
    float2 r = sm[0];
    __syncthreads();
    return r;
}

// ===================== HMMA single-pass fp16 GEMM core (128x128 tile) =======
// 4-stage cp.async ring, prefetch distance 3 (wait_group 2).
// C = A * B^T over K range [kbase, kbase + nch*32). A[M][lda], B[N][lda] fp16.
__device__ __forceinline__ void gemm_core(
    const __half* __restrict__ A, const __half* __restrict__ B,
    float* __restrict__ C, int m0, int n0, int kbase, int lda, int N, int nch,
    char* smdyn) {
    const int tid = threadIdx.x;
    const int lane = tid & 31, wid = tid >> 5;
    const int wm = wid & 3, wn = wid >> 2;

    const int lrow = tid >> 2, lc = tid & 3;
    const int lpc = lc ^ ((lrow >> 1) & 3);
    const uint32_t sb0 = smem_u32(smdyn);
    const uint32_t s_store = sb0 + lrow * 64 + lpc * 16;
    const __half* gA = A + (size_t)(m0 + lrow) * lda + kbase + lc * 8;
    const __half* gB = B + (size_t)(n0 + lrow) * lda + kbase + lc * 8;

#define LOADST(s, i) do { \
    uint32_t _so = s_store + (uint32_t)(s) * 16384u; \
    size_t _ko = (size_t)(i) * 32; \
    cp16(_so,        gA + _ko); \
    cp16(_so + 8192, gB + _ko); } while (0)

    LOADST(0, 0); CPCOMMIT;
    LOADST(1, 1); CPCOMMIT;
    LOADST(2, 2); CPCOMMIT;

    float acc[2][4][4];
    #pragma unroll
    for (int mf = 0; mf < 2; mf++)
        #pragma unroll
        for (int nf = 0; nf < 4; nf++)
            #pragma unroll
            for (int r = 0; r < 4; r++) acc[mf][nf][r] = 0.f;

    const int r15 = lane & 15, ksel = lane >> 4;

    for (int i = 0; i < nch; i++) {
        CPWAIT2;
        __syncthreads();
        uint32_t sb = sb0 + (uint32_t)(i & 3) * 16384u;
        #pragma unroll
        for (int kt = 0; kt < 2; kt++) {
            const int cA = 2 * kt + ksel;
            uint32_t a[2][4], b[2][4];
            #pragma unroll
            for (int mf = 0; mf < 2; mf++) {
                int row = wm * 32 + mf * 16 + r15;
                uint32_t off = (uint32_t)(row * 64 + ((cA ^ ((row >> 1) & 3)) * 16));
                ldsm4(a[mf], sb + off);
            }
            #pragma unroll
            for (int nf2 = 0; nf2 < 2; nf2++) {
                int row = wn * 32 + nf2 * 16 + r15;
                uint32_t off = (uint32_t)(row * 64 + ((cA ^ ((row >> 1) & 3)) * 16));
                ldsm4(b[nf2], sb + 8192 + off);
            }
            #pragma unroll
            for (int mf = 0; mf < 2; mf++)
                #pragma unroll
                for (int nf = 0; nf < 4; nf++)
                    mma_f32acc(acc[mf][nf], a[mf], b[nf >> 1][nf & 1], b[nf >> 1][2 + (nf & 1)]);
        }
        // stage (i+3)&3 == buffer (i-1)&3: last read in iter i-1, fenced by the
        // __syncthreads at the top of THIS iteration — safe to overwrite now.
        if (i + 3 < nch) LOADST((i + 3) & 3, i + 3);
        CPCOMMIT;
    }
#undef LOADST

    #pragma unroll
    for (int mf = 0; mf < 2; mf++)
        #pragma unroll
        for (int nf = 0; nf < 4; nf++) {
            int m = m0 + wm * 32 + mf * 16 + (lane >> 2);
            int n = n0 + wn * 32 + nf * 8 + (lane & 3) * 2;
            *(float2*)&C[(size_t)m * N + n] = make_float2(acc[mf][nf][0], acc[mf][nf][1]);
            *(float2*)&C[(size_t)(m + 8) * N + n] = make_float2(acc[mf][nf][2], acc[mf][nf][3]);
        }
}

// rgb GEMM: grid (4, 16, 4) splitk over K=8192
__global__ __launch_bounds__(512, 1)
void gemm_rgb(const __half* __restrict__ A, const __half* __restrict__ B,
              float* __restrict__ C) {
    extern __shared__ char smdyn[];
    gemm_core(A, B, C + (size_t)blockIdx.z * BB * 512,
              blockIdx.y * 128, blockIdx.x * 128, blockIdx.z * 2048, REPRK, 512, 64, smdyn);
}

// vW1 + qW1 packed, each splitk2. grid (4, 16, 4): z = job*2 + kz
__global__ __launch_bounds__(512, 1)
void gemm_dualA(const __half* __restrict__ xvh, const __half* __restrict__ vB,
                const __half* __restrict__ xqh, const __half* __restrict__ qB,
                float* __restrict__ t0p, float* __restrict__ qbp) {
    extern __shared__ char smdyn[];
    int job = blockIdx.z >> 1, kz = blockIdx.z & 1;
    const __half* A = job ? xqh : xvh;
    const __half* B = job ? qB : vB;
    float* C = (job ? qbp : t0p) + (size_t)kz * BB * 512;
    gemm_core(A, B, C, blockIdx.y * 128, blockIdx.x * 128, kz * 256, 512, 512, 8, smdyn);
}

// qW2 (full) + vW2 (splitk2) packed. grid (4, 416)
__global__ __launch_bounds__(512, 1)
void gemm_dualB(const __half* __restrict__ q1h, const __half* __restrict__ qB,
                const __half* __restrict__ t1h, const __half* __restrict__ vB,
                float* __restrict__ q2pre, float* __restrict__ t0p) {
    extern __shared__ char smdyn[];
    int y = blockIdx.y;
    if (y < 384) {
        gemm_core(q1h, qB, q2pre, y * 128, blockIdx.x * 128, 0, 512, 512, 16, smdyn);
    } else {
        int j = y - 384, kz = j >> 4, y2 = j & 15;
        gemm_core(t1h, vB, t0p + (size_t)kz * BB * 512,
                  y2 * 128, blockIdx.x * 128, kz * 256, 512, 512, 8, smdyn);
    }
}

// ===================== prep kernels =========================================
// rgb_obs f32 -> fp16
__global__ void conv_hi(const float* __restrict__ x, __half* __restrict__ h, int n4) {
    int i = blockIdx.x * blockDim.x + threadIdx.x;
    if (i >= n4) return;
    float4 v = ((const float4*)x)[i];
    ((__half2*)h)[i * 2]     = __halves2half2(__float2half_rn(v.x), __float2half_rn(v.y));
    ((__half2*)h)[i * 2 + 1] = __halves2half2(__float2half_rn(v.z), __float2half_rn(v.w));
}

// all four 512x512 weight transposes (f32 -> fp16) in one launch
__global__ void trans4(const float* __restrict__ W0, __half* __restrict__ T0,
                       const float* __restrict__ W1, __half* __restrict__ T1,
                       const float* __restrict__ W2, __half* __restrict__ T2,
                       const float* __restrict__ W3, __half* __restrict__ T3) {
    __shared__ float t[32][33];
    int z = blockIdx.z;
    const float* W = z == 0 ? W0 : z == 1 ? W1 : z == 2 ? W2 : W3;
    __half* T = z == 0 ? T0 : z == 1 ? T1 : z == 2 ? T2 : T3;
    int k0 = blockIdx.x * 32, n0 = blockIdx.y * 32;
    int tx = threadIdx.x, ty = threadIdx.y;
    #pragma unroll
    for (int i = 0; i < 4; i++)
        t[ty + i * 8][tx] = W[(size_t)(k0 + ty + i * 8) * 512 + n0 + tx];
    __syncthreads();
    #pragma unroll
    for (int i = 0; i < 4; i++)
        T[(size_t)(n0 + ty + i * 8) * 512 + k0 + tx] = __float2half_rn(t[tx][ty + i * 8]);
}

__global__ void trans_rgb(const float* __restrict__ vW, const float* __restrict__ qW,
                          __half* __restrict__ T) {
    __shared__ float t[32][33];
    int k0 = blockIdx.x * 32, n0 = blockIdx.y * 32;
    int tx = threadIdx.x, ty = threadIdx.y;
    const float* src = (n0 < 256) ? vW : qW;
    int nb = (n0 < 256) ? n0 : (n0 - 256);
    #pragma unroll
    for (int i = 0; i < 4; i++)
        t[ty + i * 8][tx] = src[(size_t)(k0 + ty + i * 8) * 256 + nb + tx];
    __syncthreads();
    #pragma unroll
    for (int i = 0; i < 4; i++)
        T[(size_t)(n0 + ty + i * 8) * REPRK + k0 + tx] = __float2half_rn(t[tx][ty + i * 8]);
}

// ===================== activation kernels ===================================
__global__ void ln_tanh_rgb(const float* __restrict__ part,
                            const float* __restrict__ vg, const float* __restrict__ vb,
                            const float* __restrict__ qg, const float* __restrict__ qb,
                            __half* __restrict__ xvh, __half* __restrict__ xqh) {
    int b = blockIdx.x, hsel = blockIdx.y, j = threadIdx.x;
    const size_t np = (size_t)BB * 512;
    size_t off = (size_t)b * 512 + hsel * 256 + j;
    float x = part[off] + part[off + np] + part[off + 2 * np] + part[off + 3 * np];
    float2 r = blockReduce2_256(make_float2(x, x * x));
    float mu = r.x * (1.f / 256.f);
    float inv = rsqrtf(r.y * (1.f / 256.f) - mu * mu + 1e-5f);
    const float* g  = hsel ? qg : vg;
    const float* be = hsel ? qb : vb;
    float y = tanhf((x - mu) * inv * g[j] + be[j]);
    __half* dst = hsel ? xqh : xvh;
    dst[(size_t)b * 512 + j] = __float2half_rn(y);
}

__global__ void low_kernel(const float* __restrict__ low,
                           const float* __restrict__ vW, const float* __restrict__ vg, const float* __restrict__ vb,
                           const float* __restrict__ qW, const float* __restrict__ qg, const float* __restrict__ qb,
                           __half* __restrict__ xvh, __half* __restrict__ xqh) {
    int b = blockIdx.x, j = threadIdx.x;
    __shared__ float lo[32];
    if (j < 32) lo[j] = low[b * 32 + j];
    __syncthreads();
    float sv = 0.f, sq = 0.f;
    #pragma unroll 8
    for (int k = 0; k < 32; k++) {
        float l = lo[k];
        sv += l * vW[k * 256 + j];
        sq += l * qW[k * 256 + j];
    }
    float2 rv = blockReduce2_256(make_float2(sv, sv * sv));
    float muv = rv.x * (1.f / 256.f);
    float iv  = rsqrtf(rv.y * (1.f / 256.f) - muv * muv + 1e-5f);
    xvh[(size_t)b * 512 + 256 + j] = __float2half_rn(tanhf((sv - muv) * iv * vg[j] + vb[j]));
    float2 rq = blockReduce2_256(make_float2(sq, sq * sq));
    float muq = rq.x * (1.f / 256.f);
    float iq  = rsqrtf(rq.y * (1.f / 256.f) - muq * muq + 1e-5f);
    xqh[(size_t)b * 512 + 256 + j] = __float2half_rn(tanhf((sq - muq) * iq * qg[j] + qb[j]));
}

// one thread per (b, s): contiguous 32B stores
__global__ void act_kernel(const int* __restrict__ cat, float* __restrict__ act) {
    int t = blockIdx.x * blockDim.x + threadIdx.x;
    if (t >= BB * SS) return;
    int b = t / SS, k = t - b * SS;
    int ls = k >> 3, ds = k & 7;
    float out[8];
    #pragma unroll
    for (int d = 0; d < 8; d++) {
        int lvl = ls + (d < ds ? 1 : 0);
        float lowv = -1.f, width = 2.f, mid = 0.f;
        for (int l = 0; l < lvl; l++) {
            float w = width * (1.f / 16.f);
            float c = (float)cat[(b * 3 + l) * 8 + d];
            float nl = lowv + c * w;
            mid = nl + 0.5f * w;
            lowv = nl; width = w;
        }
        out[d] = (lvl == 0) ? 0.f : mid;
    }
    float4* dst = (float4*)&act[(size_t)t * 8];
    dst[0] = make_float4(out[0], out[1], out[2], out[3]);
    dst[1] = make_float4(out[4], out[5], out[6], out[7]);
}

// blocks [0,2048): q1_all (reads qbp partials); [2048,4096): ln_silu (t0p)
__global__ __launch_bounds__(256)
void mid_k(const float* __restrict__ qbp, const float* __restrict__ act,
           const float* __restrict__ qW1, const float* __restrict__ qg1, const float* __restrict__ qb1,
           const float* __restrict__ t0p, const float* __restrict__ vg1, const float* __restrict__ vb1,
           __half* __restrict__ q1h, __half* __restrict__ t1h) {
    const size_t np = (size_t)BB * 512;
    int j = threadIdx.x;
    if (blockIdx.x < BB) {
        __shared__ float wact[8 * 512];
        __shared__ float as[SS * DD];
        int b = blockIdx.x;
        for (int i = j; i < 8 * 512; i += 256)
            wact[i] = qW1[(size_t)(512 + (i >> 9)) * 512 + (i & 511)];
        for (int i = j; i < SS * DD; i += 256)
            as[i] = act[(size_t)b * SS * DD + i];
        float b0 = qbp[(size_t)b * 512 + j]       + qbp[np + (size_t)b * 512 + j];
        float b1 = qbp[(size_t)b * 512 + 256 + j] + qbp[np + (size_t)b * 512 + 256 + j];
        float g0 = qg1[j], g1 = qg1[j + 256], e0 = qb1[j], e1 = qb1[j + 256];
        __syncthreads();
        for (int s = 0; s < SS; s++) {
            float x0 = b0, x1 = b1;
            #pragma unroll
            for (int d = 0; d < 8; d++) {
                float av = as[s * 8 + d];
                x0 += av * wact[d * 512 + j];
                x1 += av * wact[d * 512 + 256 + j];
            }
            float2 r = blockReduce2_256(make_float2(x0 + x1, x0 * x0 + x1 * x1));
            float mu = r.x * (1.f / 512.f);
            float inv = rsqrtf(r.y * (1.f / 512.f) - mu * mu + 1e-5f);
            size_t row = (size_t)s * BB + b;
            q1h[row * 512 + j]       = __float2half_rn(silu((x0 - mu) * inv * g0 + e0));
            q1h[row * 512 + 256 + j] = __float2half_rn(silu((x1 - mu) * inv * g1 + e1));
        }
    } else {
        size_t row = blockIdx.x - BB;
        float x0 = t0p[row * 512 + j]       + t0p[np + row * 512 + j];
        float x1 = t0p[row * 512 + 256 + j] + t0p[np + row * 512 + 256 + j];
        float2 r = blockReduce2_256(make_float2(x0 + x1, x0 * x0 + x1 * x1));
        float mu = r.x * (1.f / 512.f);
        float inv = rsqrtf(r.y * (1.f / 512.f) - mu * mu + 1e-5f);
        t1h[row * 512 + j]       = __float2half_rn(silu((x0 - mu) * inv * vg1[j] + vb1[j]));
        t1h[row * 512 + 256 + j] = __float2half_rn(silu((x1 - mu) * inv * vg1[j + 256] + vb1[j + 256]));
    }
}

// vW2 partials -> LN -> SiLU -> value head, one block per b
__global__ __launch_bounds__(256)
void vfin(const float* __restrict__ t0p, const float* __restrict__ g,
          const float* __restrict__ be, const float* __restrict__ Wh,
          const float* __restrict__ bh, float* __restrict__ out) {
    const size_t np = (size_t)BB * 512;
    int b = blockIdx.x, j = threadIdx.x;
    float x0 = t0p[(size_t)b * 512 + j]       + t0p[np + (size_t)b * 512 + j];
    float x1 = t0p[(size_t)b * 512 + 256 + j] + t0p[np + (size_t)b * 512 + 256 + j];
    float2 r = blockReduce2_256(make_float2(x0 + x1, x0 * x0 + x1 * x1));
    float mu = r.x * (1.f / 512.f);
    float inv = rsqrtf(r.y * (1.f / 512.f) - mu * mu + 1e-5f);
    float y0 = silu((x0 - mu) * inv * g[j] + be[j]);
    float y1 = silu((x1 - mu) * inv * g[j + 256] + be[j + 256]);
    float s = y0 * Wh[j] + y1 * Wh[256 + j];
    float2 r2 = blockReduce2_256(make_float2(s, 0.f));
    if (j == 0) out[b] = r2.x + bh[0];
}

// ---- fused LN + SiLU + diagonal q-head over q2pre (s-major rows) ----------
#define YSLD 520
__global__ __launch_bounds__(256)
void lnhead_q(const float* __restrict__ pre, const float* __restrict__ g,
              const float* __restrict__ be, const float* __restrict__ Wh,
              const float* __restrict__ bh, float* __restrict__ out) {
    extern __shared__ float sm[];
    float* whs = sm;             // [512][16]
    float* ys  = sm + 512 * 16;  // [64][YSLD]
    const int tid = threadIdx.x, lane = tid & 31, w = tid >> 5;
    const int r0 = blockIdx.x * 64;
    const int s16 = (r0 >> 11) * 16;

    for (int i = tid; i < 512 * 16; i += 256)
        whs[i] = Wh[(size_t)(i >> 4) * SBH + s16 + (i & 15)];

    for (int rr = w; rr < 64; rr += 8) {
        const float* row = pre + (size_t)(r0 + rr) * 512;
        float v[16];
        float s1 = 0.f, s2 = 0.f;
        #pragma unroll
        for (int i = 0; i < 16; i++) {
            v[i] = row[lane + i * 32];
            s1 += v[i]; s2 += v[i] * v[i];
        }
        #pragma unroll
        for (int o = 16; o > 0; o >>= 1) {
            s1 += __shfl_xor_sync(0xffffffffu, s1, o);
            s2 += __shfl_xor_sync(0xffffffffu, s2, o);
        }
        float mu = s1 * (1.f / 512.f);
        float inv = rsqrtf(s2 * (1.f / 512.f) - mu * mu + 1e-5f);
        #pragma unroll
        for (int i = 0; i < 16; i++) {
            int col = lane + i * 32;
            ys[rr * YSLD + col] = silu((v[i] - mu) * inv * g[col] + be[col]);
        }
    }
    __syncthreads();

    const int rid = tid >> 3, c2 = tid & 7;
    const float2 bias = *(const float2*)&bh[s16 + c2 * 2];
    float a0 = 0.f, a1 = 0.f, c0 = 0.f, c1 = 0.f;
    const float* y0r = ys + rid * YSLD;
    const float* y1r = ys + (rid + 32) * YSLD;
    #pragma unroll 8
    for (int k = 0; k < 512; k++) {
        float2 w2 = *(const float2*)&whs[k * 16 + c2 * 2];
        float ya = y0r[k], yb = y1r[k];
        a0 += ya * w2.x; a1 += ya * w2.y;
        c0 += yb * w2.x; c1 += yb * w2.y;
    }
    int brow0 = (r0 + rid) & (BB - 1);
    int brow1 = (r0 + rid + 32) & (BB - 1);
    *(float2*)&out[(size_t)brow0 * SBH + s16 + c2 * 2] = make_float2(a0 + bias.x, a1 + bias.y);
    *(float2*)&out[(size_t)brow1 * SBH + s16 + c2 * 2] = make_float2(c0 + bias.x, c1 + bias.y);
}

// ===================== launch ================================================
#define GEMM_DSMEM 65536
#define LNHEAD_DSMEM ((512 * 16 + 64 * YSLD) * 4)

extern "C" void kernel_launch(void* const* d_in, const int* in_sizes, int n_in,
                              void* d_out, int out_size) {
    const float* rgb_obs = (const float*)d_in[0];
    const float* low_obs = (const float*)d_in[1];
    const int*   category = (const int*)d_in[2];
    const float* v_W_rgb = (const float*)d_in[3];
    const float* v_g_rgb = (const float*)d_in[4];
    const float* v_b_rgb = (const float*)d_in[5];
    const float* v_W_low = (const float*)d_in[6];
    const float* v_g_low = (const float*)d_in[7];
    const float* v_b_low = (const float*)d_in[8];
    const float* v_W1 = (const float*)d_in[9];
    const float* v_g1 = (const float*)d_in[10];
    const float* v_b1 = (const float*)d_in[11];
    const float* v_W2 = (const float*)d_in[12];
    const float* v_g2 = (const float*)d_in[13];
    const float* v_b2 = (const float*)d_in[14];
    const float* v_Wh = (const float*)d_in[15];
    const float* v_bh = (const float*)d_in[16];
    const float* q_W_rgb = (const float*)d_in[17];
    const float* q_g_rgb = (const float*)d_in[18];
    const float* q_b_rgb = (const float*)d_in[19];
    const float* q_W_low = (const float*)d_in[20];
    const float* q_g_low = (const float*)d_in[21];
    const float* q_b_low = (const float*)d_in[22];
    const float* q_W1 = (const float*)d_in[23];
    const float* q_g1 = (const float*)d_in[24];
    const float* q_b1 = (const float*)d_in[25];
    const float* q_W2 = (const float*)d_in[26];
    const float* q_g2 = (const float*)d_in[27];
    const float* q_b2 = (const float*)d_in[28];
    const float* q_Wh = (const float*)d_in[29];
    const float* q_bh = (const float*)d_in[30];

    float* out_value = (float*)d_out;
    float* out_adv   = out_value + BB;

    cudaFuncSetAttribute(gemm_rgb,   cudaFuncAttributeMaxDynamicSharedMemorySize, GEMM_DSMEM);
    cudaFuncSetAttribute(gemm_dualA, cudaFuncAttributeMaxDynamicSharedMemorySize, GEMM_DSMEM);
    cudaFuncSetAttribute(gemm_dualB, cudaFuncAttributeMaxDynamicSharedMemorySize, GEMM_DSMEM);
    cudaFuncSetAttribute(lnhead_q,   cudaFuncAttributeMaxDynamicSharedMemorySize, LNHEAD_DSMEM);

    __half *Ahi, *WrgbT, *xvh, *xqh;
    __half *vW1T, *vW2T, *qW1T, *qW2T;
    __half *t1h, *q1h;
    float *rgb_part, *act, *q2pre;
    cudaGetSymbolAddress((void**)&Ahi, g_Ahi);
    cudaGetSymbolAddress((void**)&WrgbT, g_WrgbTh);
    cudaGetSymbolAddress((void**)&rgb_part, g_rgb_part);
    cudaGetSymbolAddress((void**)&xvh, g_xvh);
    cudaGetSymbolAddress((void**)&xqh, g_xqh);
    cudaGetSymbolAddress((void**)&vW1T, g_vW1Th);
    cudaGetSymbolAddress((void**)&vW2T, g_vW2Th);
    cudaGetSymbolAddress((void**)&qW1T, g_qW1Th);
    cudaGetSymbolAddress((void**)&qW2T, g_qW2Th);
    cudaGetSymbolAddress((void**)&t1h, g_t1h);
    cudaGetSymbolAddress((void**)&act, g_act);
    cudaGetSymbolAddress((void**)&q1h, g_q1h);
    cudaGetSymbolAddress((void**)&q2pre, g_q2pre);

    float* t0p = rgb_part;                        // slices 0,1
    float* qbp = rgb_part + 2 * (size_t)BB * 512; // slices 2,3

    // ---- prep ----
    act_kernel<<<(BB * SS + 255) / 256, 256>>>(category, act);
    conv_hi<<<(BB * REPRK / 4 + 255) / 256, 256>>>(rgb_obs, Ahi, BB * REPRK / 4);
    trans_rgb<<<dim3(REPRK / 32, 512 / 32), dim3(32, 8)>>>(v_W_rgb, q_W_rgb, WrgbT);
    trans4<<<dim3(16, 16, 4), dim3(32, 8)>>>(v_W1, vW1T, v_W2, vW2T, q_W1, qW1T, q_W2, qW2T);

    // ---- shared rgb features: split-K=4 over K=8192, reduce folded into LN ----
    gemm_rgb<<<dim3(4, BB / 128, 4), 512, GEMM_DSMEM>>>(Ahi, WrgbT, rgb_part);
    ln_tanh_rgb<<<dim3(BB, 2), 256>>>(rgb_part, v_g_rgb, v_b_rgb, q_g_rgb, q_b_rgb, xvh, xqh);
    low_kernel<<<BB, 256>>>(low_obs, v_W_low, v_g_low, v_b_low, q_W_low, q_g_low, q_b_low,
                            xvh, xqh);

    // ---- layer 1 (v + q packed, split-K=2 each) ----
    gemm_dualA<<<dim3(4, 16, 4), 512, GEMM_DSMEM>>>(xvh, vW1T, xqh, qW1T, t0p, qbp);
    // ---- q1 expansion + v ln_silu in one launch ----
    mid_k<<<2 * BB, 256>>>(qbp, act, q_W1, q_g1, q_b1, t0p, v_g1, v_b1, q1h, t1h);

    // ---- layer 2: qW2 (big) + vW2 (splitk2) packed ----
    gemm_dualB<<<dim3(4, 416), 512, GEMM_DSMEM>>>(q1h, qW2T, t1h, vW2T, q2pre, t0p);

    // ---- heads ----
    vfin<<<BB, 256>>>(t0p, v_g2, v_b2, v_Wh, v_bh, out_value);
    lnhead_q<<<(BB * SS) / 64, 256, LNHEAD_DSMEM>>>(q2pre, q_g2, q_b2, q_Wh, q_bh, out_adv);
}

// round 13
// speedup vs baseline: 1.8982x; 1.2113x over previous
#include <cuda_runtime.h>
#include <cuda_fp16.h>
#include <stdint.h>
#include <math.h>

#define BB    2048
#define REPRK 8192
#define SS    24
#define DD    8
#define SBH   384   // S*BINS

// ===================== PTX helpers (non-arch-specific) ======================
__device__ __forceinline__ uint32_t smem_u32(const void* p) {
    uint32_t a;
    asm("{ .reg .u64 t; cvta.to.shared.u64 t, %1; cvt.u32.u64 %0, t; }" : "=r"(a) : "l"(p));
    return a;
}
__device__ __forceinline__ void cp16(uint32_t saddr, const void* g) {
    asm volatile("cp.async.cg.shared.global [%0], [%1], 16;" :: "r"(saddr), "l"(g));
}
#define CPCOMMIT asm volatile("cp.async.commit_group;" ::: "memory")
#define CPWAIT2  asm volatile("cp.async.wait_group 2;" ::: "memory")

__device__ __forceinline__ void ldsm4(uint32_t* r, uint32_t addr) {
    asm volatile("ldmatrix.sync.aligned.m8n8.x4.shared.b16 {%0,%1,%2,%3}, [%4];"
        : "=r"(r[0]), "=r"(r[1]), "=r"(r[2]), "=r"(r[3]) : "r"(addr));
}
// fp16 inputs, f32 accumulator
__device__ __forceinline__ void mma_f32acc(float* d, const uint32_t* a, uint32_t b0, uint32_t b1) {
    asm volatile("mma.sync.aligned.m16n8k16.row.col.f32.f16.f16.f32 "
        "{%0,%1,%2,%3}, {%4,%5,%6,%7}, {%8,%9}, {%0,%1,%2,%3};"
        : "+f"(d[0]), "+f"(d[1]), "+f"(d[2]), "+f"(d[3])
        : "r"(a[0]), "r"(a[1]), "r"(a[2]), "r"(a[3]), "r"(b0), "r"(b1));
}

// ===================== scratch (device globals) =============================
__device__ __half g_Ahi[(size_t)BB * REPRK];       // 32 MB
__device__ __half g_WrgbTh[(size_t)512 * REPRK];   // 8 MB
__device__ float g_rgb_part[4 * BB * 512];         // 16 MB: rgb splitk, then t0p/qbp
__device__ __half g_xvh[BB * 512];
__device__ __half g_xqh[BB * 512];
__device__ __half g_vW1Th[512 * 512];
__device__ __half g_vW2Th[512 * 512];
__device__ __half g_qW1Th[512 * 512];
__device__ __half g_qW2Th[512 * 512];
__device__ __half g_t1h[BB * 512];
__device__ __half g_q1h[(size_t)BB * SS * 512];    // 50 MB (s-major rows)
__device__ __half g_q2pre[(size_t)BB * SS * 512];  // 50 MB (s-major rows, fp16)

// ===================== small helpers ========================================
__device__ __forceinline__ float silu(float z) { return z / (1.f + expf(-z)); }

__device__ __forceinline__ float2 blockReduce2_256(float2 v) {
    __shared__ float2 sm[8];
    int lane = threadIdx.x & 31, w = threadIdx.x >> 5;
    #pragma unroll
    for (int o = 16; o > 0; o >>= 1) {
        v.x += __shfl_xor_sync(0xffffffffu, v.x, o);
        v.y += __shfl_xor_sync(0xffffffffu, v.y, o);
    }
    if (lane == 0) sm[w] = v;
    __syncthreads();
    if (threadIdx.x == 0) {
        float2 t = sm[0];
        #pragma unroll
        for (int i = 1; i < 8; i++) { t.x += sm[i].x; t.y += sm[i].y; }
        sm[0] = t;
    }
    __syncthreads();
    float2 r = sm[0];
    __syncthreads();
    return r;
}

// ===================== HMMA single-pass fp16 GEMM core (128x128 tile) =======
// 4-stage cp.async ring, prefetch distance 3 (wait_group 2).
// HOUT=false: C f32 ; HOUT=true: C fp16.
template<bool HOUT>
__device__ __forceinline__ void gemm_core(
    const __half* __restrict__ A, const __half* __restrict__ B,
    void* __restrict__ Cv, int m0, int n0, int kbase, int lda, int N, int nch,
    char* smdyn) {
    const int tid = threadIdx.x;
    const int lane = tid & 31, wid = tid >> 5;
    const int wm = wid & 3, wn = wid >> 2;

    const int lrow = tid >> 2, lc = tid & 3;
    const int lpc = lc ^ ((lrow >> 1) & 3);
    const uint32_t sb0 = smem_u32(smdyn);
    const uint32_t s_store = sb0 + lrow * 64 + lpc * 16;
    const __half* gA = A + (size_t)(m0 + lrow) * lda + kbase + lc * 8;
    const __half* gB = B + (size_t)(n0 + lrow) * lda + kbase + lc * 8;

#define LOADST(s, i) do { \
    uint32_t _so = s_store + (uint32_t)(s) * 16384u; \
    size_t _ko = (size_t)(i) * 32; \
    cp16(_so,        gA + _ko); \
    cp16(_so + 8192, gB + _ko); } while (0)

    LOADST(0, 0); CPCOMMIT;
    LOADST(1, 1); CPCOMMIT;
    LOADST(2, 2); CPCOMMIT;

    float acc[2][4][4];
    #pragma unroll
    for (int mf = 0; mf < 2; mf++)
        #pragma unroll
        for (int nf = 0; nf < 4; nf++)
            #pragma unroll
            for (int r = 0; r < 4; r++) acc[mf][nf][r] = 0.f;

    const int r15 = lane & 15, ksel = lane >> 4;

    for (int i = 0; i < nch; i++) {
        CPWAIT2;
        __syncthreads();
        uint32_t sb = sb0 + (uint32_t)(i & 3) * 16384u;
        #pragma unroll
        for (int kt = 0; kt < 2; kt++) {
            const int cA = 2 * kt + ksel;
            uint32_t a[2][4], b[2][4];
            #pragma unroll
            for (int mf = 0; mf < 2; mf++) {
                int row = wm * 32 + mf * 16 + r15;
                uint32_t off = (uint32_t)(row * 64 + ((cA ^ ((row >> 1) & 3)) * 16));
                ldsm4(a[mf], sb + off);
            }
            #pragma unroll
            for (int nf2 = 0; nf2 < 2; nf2++) {
                int row = wn * 32 + nf2 * 16 + r15;
                uint32_t off = (uint32_t)(row * 64 + ((cA ^ ((row >> 1) & 3)) * 16));
                ldsm4(b[nf2], sb + 8192 + off);
            }
            #pragma unroll
            for (int mf = 0; mf < 2; mf++)
                #pragma unroll
                for (int nf = 0; nf < 4; nf++)
                    mma_f32acc(acc[mf][nf], a[mf], b[nf >> 1][nf & 1], b[nf >> 1][2 + (nf & 1)]);
        }
        if (i + 3 < nch) LOADST((i + 3) & 3, i + 3);
        CPCOMMIT;
    }
#undef LOADST

    #pragma unroll
    for (int mf = 0; mf < 2; mf++)
        #pragma unroll
        for (int nf = 0; nf < 4; nf++) {
            int m = m0 + wm * 32 + mf * 16 + (lane >> 2);
            int n = n0 + wn * 32 + nf * 8 + (lane & 3) * 2;
            if (HOUT) {
                __half* Ch = (__half*)Cv;
                *(__half2*)&Ch[(size_t)m * N + n] = __floats2half2_rn(acc[mf][nf][0], acc[mf][nf][1]);
                *(__half2*)&Ch[(size_t)(m + 8) * N + n] = __floats2half2_rn(acc[mf][nf][2], acc[mf][nf][3]);
            } else {
                float* Cf = (float*)Cv;
                *(float2*)&Cf[(size_t)m * N + n] = make_float2(acc[mf][nf][0], acc[mf][nf][1]);
                *(float2*)&Cf[(size_t)(m + 8) * N + n] = make_float2(acc[mf][nf][2], acc[mf][nf][3]);
            }
        }
}

// rgb GEMM: grid (4, 16, 4) splitk over K=8192
__global__ __launch_bounds__(512, 1)
void gemm_rgb(const __half* __restrict__ A, const __half* __restrict__ B,
              float* __restrict__ C) {
    extern __shared__ char smdyn[];
    gemm_core<false>(A, B, C + (size_t)blockIdx.z * BB * 512,
                     blockIdx.y * 128, blockIdx.x * 128, blockIdx.z * 2048, REPRK, 512, 64, smdyn);
}

// vW1 + qW1 packed, each splitk2. grid (4, 16, 4): z = job*2 + kz
__global__ __launch_bounds__(512, 1)
void gemm_dualA(const __half* __restrict__ xvh, const __half* __restrict__ vB,
                const __half* __restrict__ xqh, const __half* __restrict__ qB,
                float* __restrict__ t0p, float* __restrict__ qbp) {
    extern __shared__ char smdyn[];
    int job = blockIdx.z >> 1, kz = blockIdx.z & 1;
    const __half* A = job ? xqh : xvh;
    const __half* B = job ? qB : vB;
    float* C = (job ? qbp : t0p) + (size_t)kz * BB * 512;
    gemm_core<false>(A, B, C, blockIdx.y * 128, blockIdx.x * 128, kz * 256, 512, 512, 8, smdyn);
}

// qW2 (full, fp16 out) + vW2 (splitk2, f32 out) packed. grid (4, 416)
__global__ __launch_bounds__(512, 1)
void gemm_dualB(const __half* __restrict__ q1h, const __half* __restrict__ qB,
                const __half* __restrict__ t1h, const __half* __restrict__ vB,
                __half* __restrict__ q2pre, float* __restrict__ t0p) {
    extern __shared__ char smdyn[];
    int y = blockIdx.y;
    if (y < 384) {
        gemm_core<true>(q1h, qB, q2pre, y * 128, blockIdx.x * 128, 0, 512, 512, 16, smdyn);
    } else {
        int j = y - 384, kz = j >> 4, y2 = j & 15;
        gemm_core<false>(t1h, vB, t0p + (size_t)kz * BB * 512,
                         y2 * 128, blockIdx.x * 128, kz * 256, 512, 512, 8, smdyn);
    }
}

// ===================== prep kernels =========================================
__global__ void conv_hi(const float* __restrict__ x, __half* __restrict__ h, int n4) {
    int i = blockIdx.x * blockDim.x + threadIdx.x;
    if (i >= n4) return;
    float4 v = ((const float4*)x)[i];
    ((__half2*)h)[i * 2]     = __halves2half2(__float2half_rn(v.x), __float2half_rn(v.y));
    ((__half2*)h)[i * 2 + 1] = __halves2half2(__float2half_rn(v.z), __float2half_rn(v.w));
}

__global__ void trans4(const float* __restrict__ W0, __half* __restrict__ T0,
                       const float* __restrict__ W1, __half* __restrict__ T1,
                       const float* __restrict__ W2, __half* __restrict__ T2,
                       const float* __restrict__ W3, __half* __restrict__ T3) {
    __shared__ float t[32][33];
    int z = blockIdx.z;
    const float* W = z == 0 ? W0 : z == 1 ? W1 : z == 2 ? W2 : W3;
    __half* T = z == 0 ? T0 : z == 1 ? T1 : z == 2 ? T2 : T3;
    int k0 = blockIdx.x * 32, n0 = blockIdx.y * 32;
    int tx = threadIdx.x, ty = threadIdx.y;
    #pragma unroll
    for (int i = 0; i < 4; i++)
        t[ty + i * 8][tx] = W[(size_t)(k0 + ty + i * 8) * 512 + n0 + tx];
    __syncthreads();
    #pragma unroll
    for (int i = 0; i < 4; i++)
        T[(size_t)(n0 + ty + i * 8) * 512 + k0 + tx] = __float2half_rn(t[tx][ty + i * 8]);
}

__global__ void trans_rgb(const float* __restrict__ vW, const float* __restrict__ qW,
                          __half* __restrict__ T) {
    __shared__ float t[32][33];
    int k0 = blockIdx.x * 32, n0 = blockIdx.y * 32;
    int tx = threadIdx.x, ty = threadIdx.y;
    const float* src = (n0 < 256) ? vW : qW;
    int nb = (n0 < 256) ? n0 : (n0 - 256);
    #pragma unroll
    for (int i = 0; i < 4; i++)
        t[ty + i * 8][tx] = src[(size_t)(k0 + ty + i * 8) * 256 + nb + tx];
    __syncthreads();
    #pragma unroll
    for (int i = 0; i < 4; i++)
        T[(size_t)(n0 + ty + i * 8) * REPRK + k0 + tx] = __float2half_rn(t[tx][ty + i * 8]);
}

// ===================== activation kernels ===================================
__global__ void ln_tanh_rgb(const float* __restrict__ part,
                            const float* __restrict__ vg, const float* __restrict__ vb,
                            const float* __restrict__ qg, const float* __restrict__ qb,
                            __half* __restrict__ xvh, __half* __restrict__ xqh) {
    int b = blockIdx.x, hsel = blockIdx.y, j = threadIdx.x;
    const size_t np = (size_t)BB * 512;
    size_t off = (size_t)b * 512 + hsel * 256 + j;
    float x = part[off] + part[off + np] + part[off + 2 * np] + part[off + 3 * np];
    float2 r = blockReduce2_256(make_float2(x, x * x));
    float mu = r.x * (1.f / 256.f);
    float inv = rsqrtf(r.y * (1.f / 256.f) - mu * mu + 1e-5f);
    const float* g  = hsel ? qg : vg;
    const float* be = hsel ? qb : vb;
    float y = tanhf((x - mu) * inv * g[j] + be[j]);
    __half* dst = hsel ? xqh : xvh;
    dst[(size_t)b * 512 + j] = __float2half_rn(y);
}

// 256 blocks x 8 batch rows; both low-weight matrices cached in dynamic smem
__global__ __launch_bounds__(256)
void low_kernel(const float* __restrict__ low,
                const float* __restrict__ vW, const float* __restrict__ vg, const float* __restrict__ vb,
                const float* __restrict__ qW, const float* __restrict__ qg, const float* __restrict__ qb,
                __half* __restrict__ xvh, __half* __restrict__ xqh) {
    extern __shared__ float ws[];   // [0:8192) vW, [8192:16384) qW
    __shared__ float lo[32];
    int j = threadIdx.x;
    for (int i = j; i < 8192; i += 256) { ws[i] = vW[i]; ws[8192 + i] = qW[i]; }
    float gv = vg[j], bv = vb[j], gq = qg[j], bq = qb[j];
    __syncthreads();
    for (int bb = 0; bb < 8; bb++) {
        int b = blockIdx.x * 8 + bb;
        if (j < 32) lo[j] = low[b * 32 + j];
        __syncthreads();
        float sv = 0.f, sq = 0.f;
        #pragma unroll 8
        for (int k = 0; k < 32; k++) {
            float l = lo[k];
            sv += l * ws[k * 256 + j];
            sq += l * ws[8192 + k * 256 + j];
        }
        float2 rv = blockReduce2_256(make_float2(sv, sv * sv));
        float muv = rv.x * (1.f / 256.f);
        float iv  = rsqrtf(rv.y * (1.f / 256.f) - muv * muv + 1e-5f);
        xvh[(size_t)b * 512 + 256 + j] = __float2half_rn(tanhf((sv - muv) * iv * gv + bv));
        float2 rq = blockReduce2_256(make_float2(sq, sq * sq));
        float muq = rq.x * (1.f / 256.f);
        float iq  = rsqrtf(rq.y * (1.f / 256.f) - muq * muq + 1e-5f);
        xqh[(size_t)b * 512 + 256 + j] = __float2half_rn(tanhf((sq - muq) * iq * gq + bq));
    }
}

// blocks [0,2048): q1_all (qbp partials; actions computed inline from category);
// [2048,4096): ln_silu for v path (t0p partials)
__global__ __launch_bounds__(256)
void mid_k(const float* __restrict__ qbp, const int* __restrict__ cat,
           const float* __restrict__ qW1, const float* __restrict__ qg1, const float* __restrict__ qb1,
           const float* __restrict__ t0p, const float* __restrict__ vg1, const float* __restrict__ vb1,
           __half* __restrict__ q1h, __half* __restrict__ t1h) {
    const size_t np = (size_t)BB * 512;
    int j = threadIdx.x;
    if (blockIdx.x < BB) {
        __shared__ float wact[8 * 512];
        __shared__ float as[SS * DD];
        int b = blockIdx.x;
        for (int i = j; i < 8 * 512; i += 256)
            wact[i] = qW1[(size_t)(512 + (i >> 9)) * 512 + (i & 511)];
        if (j < SS * DD) {
            int k = j >> 3, d = j & 7;
            int ls = k >> 3, ds = k & 7;
            int lvl = ls + (d < ds ? 1 : 0);
            float lowv = -1.f, width = 2.f, mid = 0.f;
            for (int l = 0; l < lvl; l++) {
                float w = width * (1.f / 16.f);
                float c = (float)cat[(b * 3 + l) * 8 + d];
                float nl = lowv + c * w;
                mid = nl + 0.5f * w;
                lowv = nl; width = w;
            }
            as[j] = (lvl == 0) ? 0.f : mid;
        }
        float b0 = qbp[(size_t)b * 512 + j]       + qbp[np + (size_t)b * 512 + j];
        float b1 = qbp[(size_t)b * 512 + 256 + j] + qbp[np + (size_t)b * 512 + 256 + j];
        float g0 = qg1[j], g1 = qg1[j + 256], e0 = qb1[j], e1 = qb1[j + 256];
        __syncthreads();
        for (int s = 0; s < SS; s++) {
            float x0 = b0, x1 = b1;
            #pragma unroll
            for (int d = 0; d < 8; d++) {
                float av = as[s * 8 + d];
                x0 += av * wact[d * 512 + j];
                x1 += av * wact[d * 512 + 256 + j];
            }
            float2 r = blockReduce2_256(make_float2(x0 + x1, x0 * x0 + x1 * x1));
            float mu = r.x * (1.f / 512.f);
            float inv = rsqrtf(r.y * (1.f / 512.f) - mu * mu + 1e-5f);
            size_t row = (size_t)s * BB + b;
            q1h[row * 512 + j]       = __float2half_rn(silu((x0 - mu) * inv * g0 + e0));
            q1h[row * 512 + 256 + j] = __float2half_rn(silu((x1 - mu) * inv * g1 + e1));
        }
    } else {
        size_t row = blockIdx.x - BB;
        float x0 = t0p[row * 512 + j]       + t0p[np + row * 512 + j];
        float x1 = t0p[row * 512 + 256 + j] + t0p[np + row * 512 + 256 + j];
        float2 r = blockReduce2_256(make_float2(x0 + x1, x0 * x0 + x1 * x1));
        float mu = r.x * (1.f / 512.f);
        float inv = rsqrtf(r.y * (1.f / 512.f) - mu * mu + 1e-5f);
        t1h[row * 512 + j]       = __float2half_rn(silu((x0 - mu) * inv * vg1[j] + vb1[j]));
        t1h[row * 512 + 256 + j] = __float2half_rn(silu((x1 - mu) * inv * vg1[j + 256] + vb1[j + 256]));
    }
}

// vW2 partials -> LN -> SiLU -> value head, one block per b
__global__ __launch_bounds__(256)
void vfin(const float* __restrict__ t0p, const float* __restrict__ g,
          const float* __restrict__ be, const float* __restrict__ Wh,
          const float* __restrict__ bh, float* __restrict__ out) {
    const size_t np = (size_t)BB * 512;
    int b = blockIdx.x, j = threadIdx.x;
    float x0 = t0p[(size_t)b * 512 + j]       + t0p[np + (size_t)b * 512 + j];
    float x1 = t0p[(size_t)b * 512 + 256 + j] + t0p[np + (size_t)b * 512 + 256 + j];
    float2 r = blockReduce2_256(make_float2(x0 + x1, x0 * x0 + x1 * x1));
    float mu = r.x * (1.f / 512.f);
    float inv = rsqrtf(r.y * (1.f / 512.f) - mu * mu + 1e-5f);
    float y0 = silu((x0 - mu) * inv * g[j] + be[j]);
    float y1 = silu((x1 - mu) * inv * g[j + 256] + be[j + 256]);
    float s = y0 * Wh[j] + y1 * Wh[256 + j];
    float2 r2 = blockReduce2_256(make_float2(s, 0.f));
    if (j == 0) out[b] = r2.x + bh[0];
}

// ---- fused LN + SiLU + HMMA diagonal q-head over q2pre (fp16, s-major) ----
// grid 768 (64 rows, same s), 256 threads.
// dyn smem (half): whsT [16][520] + ys [64][520]; 1040-B row stride is
// conflict-free for ldmatrix (bank id = 4*row + chunk).
#define LNW 520
__global__ __launch_bounds__(256)
void lnhead_q(const __half* __restrict__ pre, const float* __restrict__ g,
              const float* __restrict__ be, const float* __restrict__ Wh,
              const float* __restrict__ bh, float* __restrict__ out) {
    extern __shared__ __half smh[];
    __half* whsT = smh;              // [16][LNW]
    __half* ys   = smh + 16 * LNW;   // [64][LNW]
    const int tid = threadIdx.x, lane = tid & 31, w = tid >> 5;
    const int r0 = blockIdx.x * 64;
    const int s16 = (r0 >> 11) * 16;

    // load Wh slice transposed: whsT[n][k] = Wh[k][s16+n]
    for (int i = tid; i < 16 * 512; i += 256) {
        int n = i & 15, k = i >> 4;
        whsT[n * LNW + k] = __float2half_rn(Wh[(size_t)k * SBH + s16 + n]);
    }

    // phase A: 8 warps x 8 rows — LN + SiLU, fp16 into ys
    for (int rr = w; rr < 64; rr += 8) {
        const __half2* row = (const __half2*)(pre + (size_t)(r0 + rr) * 512);
        float2 v[8];
        float s1 = 0.f, s2 = 0.f;
        #pragma unroll
        for (int i = 0; i < 8; i++) {
            v[i] = __half22float2(row[lane + i * 32]);
            s1 += v[i].x + v[i].y;
            s2 += v[i].x * v[i].x + v[i].y * v[i].y;
        }
        #pragma unroll
        for (int o = 16; o > 0; o >>= 1) {
            s1 += __shfl_xor_sync(0xffffffffu, s1, o);
            s2 += __shfl_xor_sync(0xffffffffu, s2, o);
        }
        float mu = s1 * (1.f / 512.f);
        float inv = rsqrtf(s2 * (1.f / 512.f) - mu * mu + 1e-5f);
        __half2* yr = (__half2*)(ys + rr * LNW);
        #pragma unroll
        for (int i = 0; i < 8; i++) {
            int col = 2 * (lane + i * 32);
            float2 gg = *(const float2*)&g[col];
            float2 bb = *(const float2*)&be[col];
            float y0 = silu((v[i].x - mu) * inv * gg.x + bb.x);
            float y1 = silu((v[i].y - mu) * inv * gg.y + bb.y);
            yr[lane + i * 32] = __floats2half2_rn(y0, y1);
        }
    }
    __syncthreads();

    // phase B: warps 0-3 each compute a 16x16 output tile via HMMA, K=512
    if (w < 4) {
        const int mt = w;
        const int r15 = lane & 15, ks = lane >> 4;
        const uint32_t abase = smem_u32(ys)   + (uint32_t)((mt * 16 + r15) * (LNW * 2) + ks * 16);
        const uint32_t bbase = smem_u32(whsT) + (uint32_t)(r15 * (LNW * 2) + ks * 16);
        float acc[2][4] = {};
        #pragma unroll 4
        for (int kk = 0; kk < 32; kk++) {
            uint32_t a[4], b[4];
            ldsm4(a, abase + kk * 32);
            ldsm4(b, bbase + kk * 32);
            mma_f32acc(acc[0], a, b[0], b[2]);
            mma_f32acc(acc[1], a, b[1], b[3]);
        }
        int rloc = mt * 16 + (lane >> 2);
        int brow0 = (r0 + rloc) & (BB - 1);
        int brow1 = (r0 + rloc + 8) & (BB - 1);
        #pragma unroll
        for (int t = 0; t < 2; t++) {
            int col = t * 8 + (lane & 3) * 2;
            float2 bias = *(const float2*)&bh[s16 + col];
            *(float2*)&out[(size_t)brow0 * SBH + s16 + col] =
                make_float2(acc[t][0] + bias.x, acc[t][1] + bias.y);
            *(float2*)&out[(size_t)brow1 * SBH + s16 + col] =
                make_float2(acc[t][2] + bias.x, acc[t][3] + bias.y);
        }
    }
}

// ===================== launch ================================================
#define GEMM_DSMEM 65536
#define LOW_DSMEM  65536
#define LNHEAD_DSMEM ((16 + 64) * LNW * 2)

extern "C" void kernel_launch(void* const* d_in, const int* in_sizes, int n_in,
                              void* d_out, int out_size) {
    const float* rgb_obs = (const float*)d_in[0];
    const float* low_obs = (const float*)d_in[1];
    const int*   category = (const int*)d_in[2];
    const float* v_W_rgb = (const float*)d_in[3];
    const float* v_g_rgb = (const float*)d_in[4];
    const float* v_b_rgb = (const float*)d_in[5];
    const float* v_W_low = (const float*)d_in[6];
    const float* v_g_low = (const float*)d_in[7];
    const float* v_b_low = (const float*)d_in[8];
    const float* v_W1 = (const float*)d_in[9];
    const float* v_g1 = (const float*)d_in[10];
    const float* v_b1 = (const float*)d_in[11];
    const float* v_W2 = (const float*)d_in[12];
    const float* v_g2 = (const float*)d_in[13];
    const float* v_b2 = (const float*)d_in[14];
    const float* v_Wh = (const float*)d_in[15];
    const float* v_bh = (const float*)d_in[16];
    const float* q_W_rgb = (const float*)d_in[17];
    const float* q_g_rgb = (const float*)d_in[18];
    const float* q_b_rgb = (const float*)d_in[19];
    const float* q_W_low = (const float*)d_in[20];
    const float* q_g_low = (const float*)d_in[21];
    const float* q_b_low = (const float*)d_in[22];
    const float* q_W1 = (const float*)d_in[23];
    const float* q_g1 = (const float*)d_in[24];
    const float* q_b1 = (const float*)d_in[25];
    const float* q_W2 = (const float*)d_in[26];
    const float* q_g2 = (const float*)d_in[27];
    const float* q_b2 = (const float*)d_in[28];
    const float* q_Wh = (const float*)d_in[29];
    const float* q_bh = (const float*)d_in[30];

    float* out_value = (float*)d_out;
    float* out_adv   = out_value + BB;

    cudaFuncSetAttribute(gemm_rgb,   cudaFuncAttributeMaxDynamicSharedMemorySize, GEMM_DSMEM);
    cudaFuncSetAttribute(gemm_dualA, cudaFuncAttributeMaxDynamicSharedMemorySize, GEMM_DSMEM);
    cudaFuncSetAttribute(gemm_dualB, cudaFuncAttributeMaxDynamicSharedMemorySize, GEMM_DSMEM);
    cudaFuncSetAttribute(low_kernel, cudaFuncAttributeMaxDynamicSharedMemorySize, LOW_DSMEM);
    cudaFuncSetAttribute(lnhead_q,   cudaFuncAttributeMaxDynamicSharedMemorySize, LNHEAD_DSMEM);

    __half *Ahi, *WrgbT, *xvh, *xqh;
    __half *vW1T, *vW2T, *qW1T, *qW2T;
    __half *t1h, *q1h, *q2pre;
    float *rgb_part;
    cudaGetSymbolAddress((void**)&Ahi, g_Ahi);
    cudaGetSymbolAddress((void**)&WrgbT, g_WrgbTh);
    cudaGetSymbolAddress((void**)&rgb_part, g_rgb_part);
    cudaGetSymbolAddress((void**)&xvh, g_xvh);
    cudaGetSymbolAddress((void**)&xqh, g_xqh);
    cudaGetSymbolAddress((void**)&vW1T, g_vW1Th);
    cudaGetSymbolAddress((void**)&vW2T, g_vW2Th);
    cudaGetSymbolAddress((void**)&qW1T, g_qW1Th);
    cudaGetSymbolAddress((void**)&qW2T, g_qW2Th);
    cudaGetSymbolAddress((void**)&t1h, g_t1h);
    cudaGetSymbolAddress((void**)&q1h, g_q1h);
    cudaGetSymbolAddress((void**)&q2pre, g_q2pre);

    float* t0p = rgb_part;                        // slices 0,1
    float* qbp = rgb_part + 2 * (size_t)BB * 512; // slices 2,3

    // ---- prep ----
    conv_hi<<<(BB * REPRK / 4 + 255) / 256, 256>>>(rgb_obs, Ahi, BB * REPRK / 4);
    trans_rgb<<<dim3(REPRK / 32, 512 / 32), dim3(32, 8)>>>(v_W_rgb, q_W_rgb, WrgbT);
    trans4<<<dim3(16, 16, 4), dim3(32, 8)>>>(v_W1, vW1T, v_W2, vW2T, q_W1, qW1T, q_W2, qW2T);

    // ---- shared rgb features: split-K=4 over K=8192, reduce folded into LN ----
    gemm_rgb<<<dim3(4, BB / 128, 4), 512, GEMM_DSMEM>>>(Ahi, WrgbT, rgb_part);
    ln_tanh_rgb<<<dim3(BB, 2), 256>>>(rgb_part, v_g_rgb, v_b_rgb, q_g_rgb, q_b_rgb, xvh, xqh);
    low_kernel<<<BB / 8, 256, LOW_DSMEM>>>(low_obs, v_W_low, v_g_low, v_b_low,
                                           q_W_low, q_g_low, q_b_low, xvh, xqh);

    // ---- layer 1 (v + q packed, split-K=2 each) ----
    gemm_dualA<<<dim3(4, 16, 4), 512, GEMM_DSMEM>>>(xvh, vW1T, xqh, qW1T, t0p, qbp);
    // ---- q1 expansion (actions inline) + v ln_silu in one launch ----
    mid_k<<<2 * BB, 256>>>(qbp, category, q_W1, q_g1, q_b1, t0p, v_g1, v_b1, q1h, t1h);

    // ---- layer 2: qW2 (big, fp16 out) + vW2 (splitk2) packed ----
    gemm_dualB<<<dim3(4, 416), 512, GEMM_DSMEM>>>(q1h, qW2T, t1h, vW2T, q2pre, t0p);

    // ---- heads ----
    vfin<<<BB, 256>>>(t0p, v_g2, v_b2, v_Wh, v_bh, out_value);
    lnhead_q<<<(BB * SS) / 64, 256, LNHEAD_DSMEM>>>(q2pre, q_g2, q_b2, q_Wh, q_bh, out_adv);
}

// round 14
// speedup vs baseline: 1.9377x; 1.0208x over previous
#include <cuda_runtime.h>
#include <cuda_fp16.h>
#include <stdint.h>
#include <math.h>

#define BB    2048
#define REPRK 8192
#define SS    24
#define DD    8
#define SBH   384   // S*BINS

// ===================== PTX helpers (non-arch-specific) ======================
__device__ __forceinline__ uint32_t smem_u32(const void* p) {
    uint32_t a;
    asm("{ .reg .u64 t; cvta.to.shared.u64 t, %1; cvt.u32.u64 %0, t; }" : "=r"(a) : "l"(p));
    return a;
}
__device__ __forceinline__ void cp16(uint32_t saddr, const void* g) {
    asm volatile("cp.async.cg.shared.global [%0], [%1], 16;" :: "r"(saddr), "l"(g));
}
#define CPCOMMIT asm volatile("cp.async.commit_group;" ::: "memory")
#define CPWAIT2  asm volatile("cp.async.wait_group 2;" ::: "memory")

__device__ __forceinline__ void ldsm4(uint32_t* r, uint32_t addr) {
    asm volatile("ldmatrix.sync.aligned.m8n8.x4.shared.b16 {%0,%1,%2,%3}, [%4];"
        : "=r"(r[0]), "=r"(r[1]), "=r"(r[2]), "=r"(r[3]) : "r"(addr));
}
// fp16 inputs, f32 accumulator
__device__ __forceinline__ void mma_f32acc(float* d, const uint32_t* a, uint32_t b0, uint32_t b1) {
    asm volatile("mma.sync.aligned.m16n8k16.row.col.f32.f16.f16.f32 "
        "{%0,%1,%2,%3}, {%4,%5,%6,%7}, {%8,%9}, {%0,%1,%2,%3};"
        : "+f"(d[0]), "+f"(d[1]), "+f"(d[2]), "+f"(d[3])
        : "r"(a[0]), "r"(a[1]), "r"(a[2]), "r"(a[3]), "r"(b0), "r"(b1));
}

// ===================== scratch (device globals) =============================
__device__ __half g_Ahi[(size_t)BB * REPRK];       // 32 MB
__device__ __half g_WrgbTh[(size_t)512 * REPRK];   // 8 MB
__device__ float g_rgb_part[4 * BB * 512];         // 16 MB: rgb splitk, then t0p/qbp
__device__ __half g_xvh[BB * 512];
__device__ __half g_xqh[BB * 512];
__device__ __half g_vW1Th[512 * 512];
__device__ __half g_vW2Th[512 * 512];
__device__ __half g_qW1Th[512 * 512];
__device__ __half g_qW2Th[512 * 512];
__device__ __half g_t1h[BB * 512];
__device__ __half g_q1h[(size_t)BB * SS * 512];    // 50 MB (s-major rows)
__device__ __half g_q2pre[(size_t)BB * SS * 512];  // 50 MB (s-major rows, fp16)

// ===================== small helpers ========================================
__device__ __forceinline__ float silu(float z) { return z / (1.f + expf(-z)); }

__device__ __forceinline__ float2 blockReduce2_256(float2 v) {
    __shared__ float2 sm[8];
    int lane = threadIdx.x & 31, w = threadIdx.x >> 5;
    #pragma unroll
    for (int o = 16; o > 0; o >>= 1) {
        v.x += __shfl_xor_sync(0xffffffffu, v.x, o);
        v.y += __shfl_xor_sync(0xffffffffu, v.y, o);
    }
    if (lane == 0) sm[w] = v;
    __syncthreads();
    if (threadIdx.x == 0) {
        float2 t = sm[0];
        #pragma unroll
        for (int i = 1; i < 8; i++) { t.x += sm[i].x; t.y += sm[i].y; }
        sm[0] = t;
    }
    __syncthreads();
    float2 r = sm[0];
    __syncthreads();
    return r;
}

// ===================== HMMA single-pass fp16 GEMM core (128x128 tile) =======
// 256 threads, 8 warps in 4x2 grid of 32x64 warp tiles.
// 4-stage cp.async ring, prefetch distance 3 (wait_group 2).
// HOUT=false: C f32 ; HOUT=true: C fp16.
template<bool HOUT>
__device__ __forceinline__ void gemm_core(
    const __half* __restrict__ A, const __half* __restrict__ B,
    void* __restrict__ Cv, int m0, int n0, int kbase, int lda, int N, int nch,
    char* smdyn) {
    const int tid = threadIdx.x;
    const int lane = tid & 31, wid = tid >> 5;
    const int wm = wid & 3, wn = wid >> 2;        // 4 x 2 warp grid

    // loaders: each thread covers rows lrow and lrow+64 of both tiles.
    // (r+64)>>1 == r>>1 + 32 ≡ r>>1 (mod 4) so the swizzle phase matches.
    const int lrow = tid >> 2, lc = tid & 3;
    const int lpc = lc ^ ((lrow >> 1) & 3);
    const uint32_t sb0 = smem_u32(smdyn);
    const uint32_t s_store = sb0 + lrow * 64 + lpc * 16;
    const __half* gA = A + (size_t)(m0 + lrow) * lda + kbase + lc * 8;
    const __half* gB = B + (size_t)(n0 + lrow) * lda + kbase + lc * 8;
    const size_t l64 = (size_t)64 * lda;

#define LOADST(s, i) do { \
    uint32_t _so = s_store + (uint32_t)(s) * 16384u; \
    size_t _ko = (size_t)(i) * 32; \
    cp16(_so,               gA + _ko); \
    cp16(_so + 4096,        gA + l64 + _ko); \
    cp16(_so + 8192,        gB + _ko); \
    cp16(_so + 8192 + 4096, gB + l64 + _ko); } while (0)

    LOADST(0, 0); CPCOMMIT;
    LOADST(1, 1); CPCOMMIT;
    LOADST(2, 2); CPCOMMIT;

    float acc[2][8][4];
    #pragma unroll
    for (int mf = 0; mf < 2; mf++)
        #pragma unroll
        for (int nf = 0; nf < 8; nf++)
            #pragma unroll
            for (int r = 0; r < 4; r++) acc[mf][nf][r] = 0.f;

    const int r15 = lane & 15, ksel = lane >> 4;

    for (int i = 0; i < nch; i++) {
        CPWAIT2;
        __syncthreads();
        uint32_t sb = sb0 + (uint32_t)(i & 3) * 16384u;
        #pragma unroll
        for (int kt = 0; kt < 2; kt++) {
            const int cA = 2 * kt + ksel;
            uint32_t a[2][4], b[4][4];
            #pragma unroll
            for (int mf = 0; mf < 2; mf++) {
                int row = wm * 32 + mf * 16 + r15;
                uint32_t off = (uint32_t)(row * 64 + ((cA ^ ((row >> 1) & 3)) * 16));
                ldsm4(a[mf], sb + off);
            }
            #pragma unroll
            for (int nf4 = 0; nf4 < 4; nf4++) {
                int row = wn * 64 + nf4 * 16 + r15;
                uint32_t off = (uint32_t)(row * 64 + ((cA ^ ((row >> 1) & 3)) * 16));
                ldsm4(b[nf4], sb + 8192 + off);
            }
            #pragma unroll
            for (int mf = 0; mf < 2; mf++)
                #pragma unroll
                for (int nf4 = 0; nf4 < 4; nf4++) {
                    mma_f32acc(acc[mf][nf4 * 2],     a[mf], b[nf4][0], b[nf4][2]);
                    mma_f32acc(acc[mf][nf4 * 2 + 1], a[mf], b[nf4][1], b[nf4][3]);
                }
        }
        if (i + 3 < nch) LOADST((i + 3) & 3, i + 3);
        CPCOMMIT;
    }
#undef LOADST

    #pragma unroll
    for (int mf = 0; mf < 2; mf++)
        #pragma unroll
        for (int nf = 0; nf < 8; nf++) {
            int m = m0 + wm * 32 + mf * 16 + (lane >> 2);
            int n = n0 + wn * 64 + nf * 8 + (lane & 3) * 2;
            if (HOUT) {
                __half* Ch = (__half*)Cv;
                *(__half2*)&Ch[(size_t)m * N + n] = __floats2half2_rn(acc[mf][nf][0], acc[mf][nf][1]);
                *(__half2*)&Ch[(size_t)(m + 8) * N + n] = __floats2half2_rn(acc[mf][nf][2], acc[mf][nf][3]);
            } else {
                float* Cf = (float*)Cv;
                *(float2*)&Cf[(size_t)m * N + n] = make_float2(acc[mf][nf][0], acc[mf][nf][1]);
                *(float2*)&Cf[(size_t)(m + 8) * N + n] = make_float2(acc[mf][nf][2], acc[mf][nf][3]);
            }
        }
}

// rgb GEMM: grid (4, 16, 4) splitk over K=8192
__global__ __launch_bounds__(256, 2)
void gemm_rgb(const __half* __restrict__ A, const __half* __restrict__ B,
              float* __restrict__ C) {
    extern __shared__ char smdyn[];
    gemm_core<false>(A, B, C + (size_t)blockIdx.z * BB * 512,
                     blockIdx.y * 128, blockIdx.x * 128, blockIdx.z * 2048, REPRK, 512, 64, smdyn);
}

// vW1 + qW1 packed, each splitk2. grid (4, 16, 4): z = job*2 + kz
__global__ __launch_bounds__(256, 2)
void gemm_dualA(const __half* __restrict__ xvh, const __half* __restrict__ vB,
                const __half* __restrict__ xqh, const __half* __restrict__ qB,
                float* __restrict__ t0p, float* __restrict__ qbp) {
    extern __shared__ char smdyn[];
    int job = blockIdx.z >> 1, kz = blockIdx.z & 1;
    const __half* A = job ? xqh : xvh;
    const __half* B = job ? qB : vB;
    float* C = (job ? qbp : t0p) + (size_t)kz * BB * 512;
    gemm_core<false>(A, B, C, blockIdx.y * 128, blockIdx.x * 128, kz * 256, 512, 512, 8, smdyn);
}

// qW2 (full, fp16 out) + vW2 (splitk2, f32 out) packed. grid (4, 416)
__global__ __launch_bounds__(256, 2)
void gemm_dualB(const __half* __restrict__ q1h, const __half* __restrict__ qB,
                const __half* __restrict__ t1h, const __half* __restrict__ vB,
                __half* __restrict__ q2pre, float* __restrict__ t0p) {
    extern __shared__ char smdyn[];
    int y = blockIdx.y;
    if (y < 384) {
        gemm_core<true>(q1h, qB, q2pre, y * 128, blockIdx.x * 128, 0, 512, 512, 16, smdyn);
    } else {
        int j = y - 384, kz = j >> 4, y2 = j & 15;
        gemm_core<false>(t1h, vB, t0p + (size_t)kz * BB * 512,
                         y2 * 128, blockIdx.x * 128, kz * 256, 512, 512, 8, smdyn);
    }
}

// ===================== prep kernels =========================================
__global__ void conv_hi(const float* __restrict__ x, __half* __restrict__ h, int n4) {
    int i = blockIdx.x * blockDim.x + threadIdx.x;
    if (i >= n4) return;
    float4 v = ((const float4*)x)[i];
    ((__half2*)h)[i * 2]     = __halves2half2(__float2half_rn(v.x), __float2half_rn(v.y));
    ((__half2*)h)[i * 2 + 1] = __halves2half2(__float2half_rn(v.z), __float2half_rn(v.w));
}

__global__ void trans4(const float* __restrict__ W0, __half* __restrict__ T0,
                       const float* __restrict__ W1, __half* __restrict__ T1,
                       const float* __restrict__ W2, __half* __restrict__ T2,
                       const float* __restrict__ W3, __half* __restrict__ T3) {
    __shared__ float t[32][33];
    int z = blockIdx.z;
    const float* W = z == 0 ? W0 : z == 1 ? W1 : z == 2 ? W2 : W3;
    __half* T = z == 0 ? T0 : z == 1 ? T1 : z == 2 ? T2 : T3;
    int k0 = blockIdx.x * 32, n0 = blockIdx.y * 32;
    int tx = threadIdx.x, ty = threadIdx.y;
    #pragma unroll
    for (int i = 0; i < 4; i++)
        t[ty + i * 8][tx] = W[(size_t)(k0 + ty + i * 8) * 512 + n0 + tx];
    __syncthreads();
    #pragma unroll
    for (int i = 0; i < 4; i++)
        T[(size_t)(n0 + ty + i * 8) * 512 + k0 + tx] = __float2half_rn(t[tx][ty + i * 8]);
}

__global__ void trans_rgb(const float* __restrict__ vW, const float* __restrict__ qW,
                          __half* __restrict__ T) {
    __shared__ float t[32][33];
    int k0 = blockIdx.x * 32, n0 = blockIdx.y * 32;
    int tx = threadIdx.x, ty = threadIdx.y;
    const float* src = (n0 < 256) ? vW : qW;
    int nb = (n0 < 256) ? n0 : (n0 - 256);
    #pragma unroll
    for (int i = 0; i < 4; i++)
        t[ty + i * 8][tx] = src[(size_t)(k0 + ty + i * 8) * 256 + nb + tx];
    __syncthreads();
    #pragma unroll
    for (int i = 0; i < 4; i++)
        T[(size_t)(n0 + ty + i * 8) * REPRK + k0 + tx] = __float2half_rn(t[tx][ty + i * 8]);
}

// ===================== activation kernels ===================================
__global__ void ln_tanh_rgb(const float* __restrict__ part,
                            const float* __restrict__ vg, const float* __restrict__ vb,
                            const float* __restrict__ qg, const float* __restrict__ qb,
                            __half* __restrict__ xvh, __half* __restrict__ xqh) {
    int b = blockIdx.x, hsel = blockIdx.y, j = threadIdx.x;
    const size_t np = (size_t)BB * 512;
    size_t off = (size_t)b * 512 + hsel * 256 + j;
    float x = part[off] + part[off + np] + part[off + 2 * np] + part[off + 3 * np];
    float2 r = blockReduce2_256(make_float2(x, x * x));
    float mu = r.x * (1.f / 256.f);
    float inv = rsqrtf(r.y * (1.f / 256.f) - mu * mu + 1e-5f);
    const float* g  = hsel ? qg : vg;
    const float* be = hsel ? qb : vb;
    float y = tanhf((x - mu) * inv * g[j] + be[j]);
    __half* dst = hsel ? xqh : xvh;
    dst[(size_t)b * 512 + j] = __float2half_rn(y);
}

// 256 blocks x 8 batch rows; both low-weight matrices cached in dynamic smem
__global__ __launch_bounds__(256)
void low_kernel(const float* __restrict__ low,
                const float* __restrict__ vW, const float* __restrict__ vg, const float* __restrict__ vb,
                const float* __restrict__ qW, const float* __restrict__ qg, const float* __restrict__ qb,
                __half* __restrict__ xvh, __half* __restrict__ xqh) {
    extern __shared__ float ws[];   // [0:8192) vW, [8192:16384) qW
    __shared__ float lo[32];
    int j = threadIdx.x;
    for (int i = j; i < 8192; i += 256) { ws[i] = vW[i]; ws[8192 + i] = qW[i]; }
    float gv = vg[j], bv = vb[j], gq = qg[j], bq = qb[j];
    __syncthreads();
    for (int bb = 0; bb < 8; bb++) {
        int b = blockIdx.x * 8 + bb;
        if (j < 32) lo[j] = low[b * 32 + j];
        __syncthreads();
        float sv = 0.f, sq = 0.f;
        #pragma unroll 8
        for (int k = 0; k < 32; k++) {
            float l = lo[k];
            sv += l * ws[k * 256 + j];
            sq += l * ws[8192 + k * 256 + j];
        }
        float2 rv = blockReduce2_256(make_float2(sv, sv * sv));
        float muv = rv.x * (1.f / 256.f);
        float iv  = rsqrtf(rv.y * (1.f / 256.f) - muv * muv + 1e-5f);
        xvh[(size_t)b * 512 + 256 + j] = __float2half_rn(tanhf((sv - muv) * iv * gv + bv));
        float2 rq = blockReduce2_256(make_float2(sq, sq * sq));
        float muq = rq.x * (1.f / 256.f);
        float iq  = rsqrtf(rq.y * (1.f / 256.f) - muq * muq + 1e-5f);
        xqh[(size_t)b * 512 + 256 + j] = __float2half_rn(tanhf((sq - muq) * iq * gq + bq));
    }
}

// blocks [0,2048): q1_all (qbp partials; actions computed inline from category);
// [2048,4096): ln_silu for v path (t0p partials)
__global__ __launch_bounds__(256)
void mid_k(const float* __restrict__ qbp, const int* __restrict__ cat,
           const float* __restrict__ qW1, const float* __restrict__ qg1, const float* __restrict__ qb1,
           const float* __restrict__ t0p, const float* __restrict__ vg1, const float* __restrict__ vb1,
           __half* __restrict__ q1h, __half* __restrict__ t1h) {
    const size_t np = (size_t)BB * 512;
    int j = threadIdx.x;
    if (blockIdx.x < BB) {
        __shared__ float wact[8 * 512];
        __shared__ float as[SS * DD];
        int b = blockIdx.x;
        for (int i = j; i < 8 * 512; i += 256)
            wact[i] = qW1[(size_t)(512 + (i >> 9)) * 512 + (i & 511)];
        if (j < SS * DD) {
            int k = j >> 3, d = j & 7;
            int ls = k >> 3, ds = k & 7;
            int lvl = ls + (d < ds ? 1 : 0);
            float lowv = -1.f, width = 2.f, mid = 0.f;
            for (int l = 0; l < lvl; l++) {
                float w = width * (1.f / 16.f);
                float c = (float)cat[(b * 3 + l) * 8 + d];
                float nl = lowv + c * w;
                mid = nl + 0.5f * w;
                lowv = nl; width = w;
            }
            as[j] = (lvl == 0) ? 0.f : mid;
        }
        float b0 = qbp[(size_t)b * 512 + j]       + qbp[np + (size_t)b * 512 + j];
        float b1 = qbp[(size_t)b * 512 + 256 + j] + qbp[np + (size_t)b * 512 + 256 + j];
        float g0 = qg1[j], g1 = qg1[j + 256], e0 = qb1[j], e1 = qb1[j + 256];
        __syncthreads();
        for (int s = 0; s < SS; s++) {
            float x0 = b0, x1 = b1;
            #pragma unroll
            for (int d = 0; d < 8; d++) {
                float av = as[s * 8 + d];
                x0 += av * wact[d * 512 + j];
                x1 += av * wact[d * 512 + 256 + j];
            }
            float2 r = blockReduce2_256(make_float2(x0 + x1, x0 * x0 + x1 * x1));
            float mu = r.x * (1.f / 512.f);
            float inv = rsqrtf(r.y * (1.f / 512.f) - mu * mu + 1e-5f);
            size_t row = (size_t)s * BB + b;
            q1h[row * 512 + j]       = __float2half_rn(silu((x0 - mu) * inv * g0 + e0));
            q1h[row * 512 + 256 + j] = __float2half_rn(silu((x1 - mu) * inv * g1 + e1));
        }
    } else {
        size_t row = blockIdx.x - BB;
        float x0 = t0p[row * 512 + j]       + t0p[np + row * 512 + j];
        float x1 = t0p[row * 512 + 256 + j] + t0p[np + row * 512 + 256 + j];
        float2 r = blockReduce2_256(make_float2(x0 + x1, x0 * x0 + x1 * x1));
        float mu = r.x * (1.f / 512.f);
        float inv = rsqrtf(r.y * (1.f / 512.f) - mu * mu + 1e-5f);
        t1h[row * 512 + j]       = __float2half_rn(silu((x0 - mu) * inv * vg1[j] + vb1[j]));
        t1h[row * 512 + 256 + j] = __float2half_rn(silu((x1 - mu) * inv * vg1[j + 256] + vb1[j + 256]));
    }
}

// vW2 partials -> LN -> SiLU -> value head, one block per b
__global__ __launch_bounds__(256)
void vfin(const float* __restrict__ t0p, const float* __restrict__ g,
          const float* __restrict__ be, const float* __restrict__ Wh,
          const float* __restrict__ bh, float* __restrict__ out) {
    const size_t np = (size_t)BB * 512;
    int b = blockIdx.x, j = threadIdx.x;
    float x0 = t0p[(size_t)b * 512 + j]       + t0p[np + (size_t)b * 512 + j];
    float x1 = t0p[(size_t)b * 512 + 256 + j] + t0p[np + (size_t)b * 512 + 256 + j];
    float2 r = blockReduce2_256(make_float2(x0 + x1, x0 * x0 + x1 * x1));
    float mu = r.x * (1.f / 512.f);
    float inv = rsqrtf(r.y * (1.f / 512.f) - mu * mu + 1e-5f);
    float y0 = silu((x0 - mu) * inv * g[j] + be[j]);
    float y1 = silu((x1 - mu) * inv * g[j + 256] + be[j + 256]);
    float s = y0 * Wh[j] + y1 * Wh[256 + j];
    float2 r2 = blockReduce2_256(make_float2(s, 0.f));
    if (j == 0) out[b] = r2.x + bh[0];
}

// ---- fused LN + SiLU + HMMA diagonal q-head over q2pre (fp16, s-major) ----
#define LNW 520
__global__ __launch_bounds__(256)
void lnhead_q(const __half* __restrict__ pre, const float* __restrict__ g,
              const float* __restrict__ be, const float* __restrict__ Wh,
              const float* __restrict__ bh, float* __restrict__ out) {
    extern __shared__ __half smh[];
    __half* whsT = smh;              // [16][LNW]
    __half* ys   = smh + 16 * LNW;   // [64][LNW]
    const int tid = threadIdx.x, lane = tid & 31, w = tid >> 5;
    const int r0 = blockIdx.x * 64;
    const int s16 = (r0 >> 11) * 16;

    for (int i = tid; i < 16 * 512; i += 256) {
        int n = i & 15, k = i >> 4;
        whsT[n * LNW + k] = __float2half_rn(Wh[(size_t)k * SBH + s16 + n]);
    }

    for (int rr = w; rr < 64; rr += 8) {
        const __half2* row = (const __half2*)(pre + (size_t)(r0 + rr) * 512);
        float2 v[8];
        float s1 = 0.f, s2 = 0.f;
        #pragma unroll
        for (int i = 0; i < 8; i++) {
            v[i] = __half22float2(row[lane + i * 32]);
            s1 += v[i].x + v[i].y;
            s2 += v[i].x * v[i].x + v[i].y * v[i].y;
        }
        #pragma unroll
        for (int o = 16; o > 0; o >>= 1) {
            s1 += __shfl_xor_sync(0xffffffffu, s1, o);
            s2 += __shfl_xor_sync(0xffffffffu, s2, o);
        }
        float mu = s1 * (1.f / 512.f);
        float inv = rsqrtf(s2 * (1.f / 512.f) - mu * mu + 1e-5f);
        __half2* yr = (__half2*)(ys + rr * LNW);
        #pragma unroll
        for (int i = 0; i < 8; i++) {
            int col = 2 * (lane + i * 32);
            float2 gg = *(const float2*)&g[col];
            float2 bb = *(const float2*)&be[col];
            float y0 = silu((v[i].x - mu) * inv * gg.x + bb.x);
            float y1 = silu((v[i].y - mu) * inv * gg.y + bb.y);
            yr[lane + i * 32] = __floats2half2_rn(y0, y1);
        }
    }
    __syncthreads();

    if (w < 4) {
        const int mt = w;
        const int r15 = lane & 15, ks = lane >> 4;
        const uint32_t abase = smem_u32(ys)   + (uint32_t)((mt * 16 + r15) * (LNW * 2) + ks * 16);
        const uint32_t bbase = smem_u32(whsT) + (uint32_t)(r15 * (LNW * 2) + ks * 16);
        float acc[2][4] = {};
        #pragma unroll 4
        for (int kk = 0; kk < 32; kk++) {
            uint32_t a[4], b[4];
            ldsm4(a, abase + kk * 32);
            ldsm4(b, bbase + kk * 32);
            mma_f32acc(acc[0], a, b[0], b[2]);
            mma_f32acc(acc[1], a, b[1], b[3]);
        }
        int rloc = mt * 16 + (lane >> 2);
        int brow0 = (r0 + rloc) & (BB - 1);
        int brow1 = (r0 + rloc + 8) & (BB - 1);
        #pragma unroll
        for (int t = 0; t < 2; t++) {
            int col = t * 8 + (lane & 3) * 2;
            float2 bias = *(const float2*)&bh[s16 + col];
            *(float2*)&out[(size_t)brow0 * SBH + s16 + col] =
                make_float2(acc[t][0] + bias.x, acc[t][1] + bias.y);
            *(float2*)&out[(size_t)brow1 * SBH + s16 + col] =
                make_float2(acc[t][2] + bias.x, acc[t][3] + bias.y);
        }
    }
}

// ===================== launch ================================================
#define GEMM_DSMEM 65536
#define LOW_DSMEM  65536
#define LNHEAD_DSMEM ((16 + 64) * LNW * 2)

extern "C" void kernel_launch(void* const* d_in, const int* in_sizes, int n_in,
                              void* d_out, int out_size) {
    const float* rgb_obs = (const float*)d_in[0];
    const float* low_obs = (const float*)d_in[1];
    const int*   category = (const int*)d_in[2];
    const float* v_W_rgb = (const float*)d_in[3];
    const float* v_g_rgb = (const float*)d_in[4];
    const float* v_b_rgb = (const float*)d_in[5];
    const float* v_W_low = (const float*)d_in[6];
    const float* v_g_low = (const float*)d_in[7];
    const float* v_b_low = (const float*)d_in[8];
    const float* v_W1 = (const float*)d_in[9];
    const float* v_g1 = (const float*)d_in[10];
    const float* v_b1 = (const float*)d_in[11];
    const float* v_W2 = (const float*)d_in[12];
    const float* v_g2 = (const float*)d_in[13];
    const float* v_b2 = (const float*)d_in[14];
    const float* v_Wh = (const float*)d_in[15];
    const float* v_bh = (const float*)d_in[16];
    const float* q_W_rgb = (const float*)d_in[17];
    const float* q_g_rgb = (const float*)d_in[18];
    const float* q_b_rgb = (const float*)d_in[19];
    const float* q_W_low = (const float*)d_in[20];
    const float* q_g_low = (const float*)d_in[21];
    const float* q_b_low = (const float*)d_in[22];
    const float* q_W1 = (const float*)d_in[23];
    const float* q_g1 = (const float*)d_in[24];
    const float* q_b1 = (const float*)d_in[25];
    const float* q_W2 = (const float*)d_in[26];
    const float* q_g2 = (const float*)d_in[27];
    const float* q_b2 = (const float*)d_in[28];
    const float* q_Wh = (const float*)d_in[29];
    const float* q_bh = (const float*)d_in[30];

    float* out_value = (float*)d_out;
    float* out_adv   = out_value + BB;

    cudaFuncSetAttribute(gemm_rgb,   cudaFuncAttributeMaxDynamicSharedMemorySize, GEMM_DSMEM);
    cudaFuncSetAttribute(gemm_dualA, cudaFuncAttributeMaxDynamicSharedMemorySize, GEMM_DSMEM);
    cudaFuncSetAttribute(gemm_dualB, cudaFuncAttributeMaxDynamicSharedMemorySize, GEMM_DSMEM);
    cudaFuncSetAttribute(low_kernel, cudaFuncAttributeMaxDynamicSharedMemorySize, LOW_DSMEM);
    cudaFuncSetAttribute(lnhead_q,   cudaFuncAttributeMaxDynamicSharedMemorySize, LNHEAD_DSMEM);

    __half *Ahi, *WrgbT, *xvh, *xqh;
    __half *vW1T, *vW2T, *qW1T, *qW2T;
    __half *t1h, *q1h, *q2pre;
    float *rgb_part;
    cudaGetSymbolAddress((void**)&Ahi, g_Ahi);
    cudaGetSymbolAddress((void**)&WrgbT, g_WrgbTh);
    cudaGetSymbolAddress((void**)&rgb_part, g_rgb_part);
    cudaGetSymbolAddress((void**)&xvh, g_xvh);
    cudaGetSymbolAddress((void**)&xqh, g_xqh);
    cudaGetSymbolAddress((void**)&vW1T, g_vW1Th);
    cudaGetSymbolAddress((void**)&vW2T, g_vW2Th);
    cudaGetSymbolAddress((void**)&qW1T, g_qW1Th);
    cudaGetSymbolAddress((void**)&qW2T, g_qW2Th);
    cudaGetSymbolAddress((void**)&t1h, g_t1h);
    cudaGetSymbolAddress((void**)&q1h, g_q1h);
    cudaGetSymbolAddress((void**)&q2pre, g_q2pre);

    float* t0p = rgb_part;                        // slices 0,1
    float* qbp = rgb_part + 2 * (size_t)BB * 512; // slices 2,3

    // ---- prep ----
    conv_hi<<<(BB * REPRK / 4 + 255) / 256, 256>>>(rgb_obs, Ahi, BB * REPRK / 4);
    trans_rgb<<<dim3(REPRK / 32, 512 / 32), dim3(32, 8)>>>(v_W_rgb, q_W_rgb, WrgbT);
    trans4<<<dim3(16, 16, 4), dim3(32, 8)>>>(v_W1, vW1T, v_W2, vW2T, q_W1, qW1T, q_W2, qW2T);

    // ---- shared rgb features: split-K=4 over K=8192, reduce folded into LN ----
    gemm_rgb<<<dim3(4, BB / 128, 4), 256, GEMM_DSMEM>>>(Ahi, WrgbT, rgb_part);
    ln_tanh_rgb<<<dim3(BB, 2), 256>>>(rgb_part, v_g_rgb, v_b_rgb, q_g_rgb, q_b_rgb, xvh, xqh);
    low_kernel<<<BB / 8, 256, LOW_DSMEM>>>(low_obs, v_W_low, v_g_low, v_b_low,
                                           q_W_low, q_g_low, q_b_low, xvh, xqh);

    // ---- layer 1 (v + q packed, split-K=2 each) ----
    gemm_dualA<<<dim3(4, 16, 4), 256, GEMM_DSMEM>>>(xvh, vW1T, xqh, qW1T, t0p, qbp);
    // ---- q1 expansion (actions inline) + v ln_silu in one launch ----
    mid_k<<<2 * BB, 256>>>(qbp, category, q_W1, q_g1, q_b1, t0p, v_g1, v_b1, q1h, t1h);

    // ---- layer 2: qW2 (big, fp16 out) + vW2 (splitk2) packed ----
    gemm_dualB<<<dim3(4, 416), 256, GEMM_DSMEM>>>(q1h, qW2T, t1h, vW2T, q2pre, t0p);

    // ---- heads ----
    vfin<<<BB, 256>>>(t0p, v_g2, v_b2, v_Wh, v_bh, out_value);
    lnhead_q<<<(BB * SS) / 64, 256, LNHEAD_DSMEM>>>(q2pre, q_g2, q_b2, q_Wh, q_bh, out_adv);
}

// round 15
// speedup vs baseline: 2.0257x; 1.0454x over previous
#include <cuda_runtime.h>
#include <cuda_fp16.h>
#include <stdint.h>
#include <math.h>

#define BB    2048
#define REPRK 8192
#define SS    24
#define DD    8
#define SBH   384   // S*BINS

// ===================== PTX helpers (non-arch-specific) ======================
__device__ __forceinline__ uint32_t smem_u32(const void* p) {
    uint32_t a;
    asm("{ .reg .u64 t; cvta.to.shared.u64 t, %1; cvt.u32.u64 %0, t; }" : "=r"(a) : "l"(p));
    return a;
}
__device__ __forceinline__ void cp16(uint32_t saddr, const void* g) {
    asm volatile("cp.async.cg.shared.global [%0], [%1], 16;" :: "r"(saddr), "l"(g));
}
#define CPCOMMIT asm volatile("cp.async.commit_group;" ::: "memory")
#define CPWAIT2  asm volatile("cp.async.wait_group 2;" ::: "memory")

__device__ __forceinline__ void ldsm4(uint32_t* r, uint32_t addr) {
    asm volatile("ldmatrix.sync.aligned.m8n8.x4.shared.b16 {%0,%1,%2,%3}, [%4];"
        : "=r"(r[0]), "=r"(r[1]), "=r"(r[2]), "=r"(r[3]) : "r"(addr));
}
__device__ __forceinline__ void mma_f32acc(float* d, const uint32_t* a, uint32_t b0, uint32_t b1) {
    asm volatile("mma.sync.aligned.m16n8k16.row.col.f32.f16.f16.f32 "
        "{%0,%1,%2,%3}, {%4,%5,%6,%7}, {%8,%9}, {%0,%1,%2,%3};"
        : "+f"(d[0]), "+f"(d[1]), "+f"(d[2]), "+f"(d[3])
        : "r"(a[0]), "r"(a[1]), "r"(a[2]), "r"(a[3]), "r"(b0), "r"(b1));
}

// ===================== scratch (device globals) =============================
__device__ __half g_Ahi[(size_t)BB * REPRK];       // 32 MB
__device__ __half g_WrgbTh[(size_t)512 * REPRK];   // 8 MB
__device__ float g_rgb_part[4 * BB * 512];         // 16 MB: rgb splitk, then t0p/qbp
__device__ __half g_xvh[BB * 512];
__device__ __half g_xqh[BB * 512];
__device__ __half g_vW1Th[512 * 512];
__device__ __half g_vW2Th[512 * 512];
__device__ __half g_qW1Th[512 * 512];
__device__ __half g_qW2Th[512 * 512];
__device__ __half g_t1h[BB * 512];
__device__ __half g_q1h[(size_t)BB * SS * 512];    // 50 MB (s-major rows)
__device__ __half g_q2pre[(size_t)BB * SS * 512];  // 50 MB (s-major rows, fp16)

// ===================== small helpers ========================================
__device__ __forceinline__ float silu(float z) { return z / (1.f + expf(-z)); }

// ===================== HMMA single-pass fp16 GEMM core (128x128 tile) =======
// 256 threads, 8 warps in 4x2 grid of 32x64 warp tiles. 4-stage ring.
template<bool HOUT>
__device__ __forceinline__ void gemm_core(
    const __half* __restrict__ A, const __half* __restrict__ B,
    void* __restrict__ Cv, int m0, int n0, int kbase, int lda, int N, int nch,
    char* smdyn) {
    const int tid = threadIdx.x;
    const int lane = tid & 31, wid = tid >> 5;
    const int wm = wid & 3, wn = wid >> 2;

    const int lrow = tid >> 2, lc = tid & 3;
    const int lpc = lc ^ ((lrow >> 1) & 3);
    const uint32_t sb0 = smem_u32(smdyn);
    const uint32_t s_store = sb0 + lrow * 64 + lpc * 16;
    const __half* gA = A + (size_t)(m0 + lrow) * lda + kbase + lc * 8;
    const __half* gB = B + (size_t)(n0 + lrow) * lda + kbase + lc * 8;
    const size_t l64 = (size_t)64 * lda;

#define LOADST(s, i) do { \
    uint32_t _so = s_store + (uint32_t)(s) * 16384u; \
    size_t _ko = (size_t)(i) * 32; \
    cp16(_so,               gA + _ko); \
    cp16(_so + 4096,        gA + l64 + _ko); \
    cp16(_so + 8192,        gB + _ko); \
    cp16(_so + 8192 + 4096, gB + l64 + _ko); } while (0)

    LOADST(0, 0); CPCOMMIT;
    LOADST(1, 1); CPCOMMIT;
    LOADST(2, 2); CPCOMMIT;

    float acc[2][8][4];
    #pragma unroll
    for (int mf = 0; mf < 2; mf++)
        #pragma unroll
        for (int nf = 0; nf < 8; nf++)
            #pragma unroll
            for (int r = 0; r < 4; r++) acc[mf][nf][r] = 0.f;

    const int r15 = lane & 15, ksel = lane >> 4;

    for (int i = 0; i < nch; i++) {
        CPWAIT2;
        __syncthreads();
        uint32_t sb = sb0 + (uint32_t)(i & 3) * 16384u;
        #pragma unroll
        for (int kt = 0; kt < 2; kt++) {
            const int cA = 2 * kt + ksel;
            uint32_t a[2][4], b[4][4];
            #pragma unroll
            for (int mf = 0; mf < 2; mf++) {
                int row = wm * 32 + mf * 16 + r15;
                uint32_t off = (uint32_t)(row * 64 + ((cA ^ ((row >> 1) & 3)) * 16));
                ldsm4(a[mf], sb + off);
            }
            #pragma unroll
            for (int nf4 = 0; nf4 < 4; nf4++) {
                int row = wn * 64 + nf4 * 16 + r15;
                uint32_t off = (uint32_t)(row * 64 + ((cA ^ ((row >> 1) & 3)) * 16));
                ldsm4(b[nf4], sb + 8192 + off);
            }
            #pragma unroll
            for (int mf = 0; mf < 2; mf++)
                #pragma unroll
                for (int nf4 = 0; nf4 < 4; nf4++) {
                    mma_f32acc(acc[mf][nf4 * 2],     a[mf], b[nf4][0], b[nf4][2]);
                    mma_f32acc(acc[mf][nf4 * 2 + 1], a[mf], b[nf4][1], b[nf4][3]);
                }
        }
        if (i + 3 < nch) LOADST((i + 3) & 3, i + 3);
        CPCOMMIT;
    }
#undef LOADST

    #pragma unroll
    for (int mf = 0; mf < 2; mf++)
        #pragma unroll
        for (int nf = 0; nf < 8; nf++) {
            int m = m0 + wm * 32 + mf * 16 + (lane >> 2);
            int n = n0 + wn * 64 + nf * 8 + (lane & 3) * 2;
            if (HOUT) {
                __half* Ch = (__half*)Cv;
                *(__half2*)&Ch[(size_t)m * N + n] = __floats2half2_rn(acc[mf][nf][0], acc[mf][nf][1]);
                *(__half2*)&Ch[(size_t)(m + 8) * N + n] = __floats2half2_rn(acc[mf][nf][2], acc[mf][nf][3]);
            } else {
                float* Cf = (float*)Cv;
                *(float2*)&Cf[(size_t)m * N + n] = make_float2(acc[mf][nf][0], acc[mf][nf][1]);
                *(float2*)&Cf[(size_t)(m + 8) * N + n] = make_float2(acc[mf][nf][2], acc[mf][nf][3]);
            }
        }
}

__global__ __launch_bounds__(256, 2)
void gemm_rgb(const __half* __restrict__ A, const __half* __restrict__ B,
              float* __restrict__ C) {
    extern __shared__ char smdyn[];
    gemm_core<false>(A, B, C + (size_t)blockIdx.z * BB * 512,
                     blockIdx.y * 128, blockIdx.x * 128, blockIdx.z * 2048, REPRK, 512, 64, smdyn);
}

__global__ __launch_bounds__(256, 2)
void gemm_dualA(const __half* __restrict__ xvh, const __half* __restrict__ vB,
                const __half* __restrict__ xqh, const __half* __restrict__ qB,
                float* __restrict__ t0p, float* __restrict__ qbp) {
    extern __shared__ char smdyn[];
    int job = blockIdx.z >> 1, kz = blockIdx.z & 1;
    const __half* A = job ? xqh : xvh;
    const __half* B = job ? qB : vB;
    float* C = (job ? qbp : t0p) + (size_t)kz * BB * 512;
    gemm_core<false>(A, B, C, blockIdx.y * 128, blockIdx.x * 128, kz * 256, 512, 512, 8, smdyn);
}

__global__ __launch_bounds__(256, 2)
void gemm_dualB(const __half* __restrict__ q1h, const __half* __restrict__ qB,
                const __half* __restrict__ t1h, const __half* __restrict__ vB,
                __half* __restrict__ q2pre, float* __restrict__ t0p) {
    extern __shared__ char smdyn[];
    int y = blockIdx.y;
    if (y < 384) {
        gemm_core<true>(q1h, qB, q2pre, y * 128, blockIdx.x * 128, 0, 512, 512, 16, smdyn);
    } else {
        int j = y - 384, kz = j >> 4, y2 = j & 15;
        gemm_core<false>(t1h, vB, t0p + (size_t)kz * BB * 512,
                         y2 * 128, blockIdx.x * 128, kz * 256, 512, 512, 8, smdyn);
    }
}

// ===================== merged prep (conv + both transposes) =================
// blocks [0,16384): conv_hi ; [16384,20480): trans_rgb ; [20480,21504): trans4
#define NB_CONV 16384
#define NB_TRGB 4096
__global__ __launch_bounds__(256)
void prep_all(const float* __restrict__ rgb, __half* __restrict__ Ah,
              const float* __restrict__ vWr, const float* __restrict__ qWr, __half* __restrict__ Trgb,
              const float* __restrict__ W0, __half* __restrict__ T0,
              const float* __restrict__ W1, __half* __restrict__ T1,
              const float* __restrict__ W2, __half* __restrict__ T2,
              const float* __restrict__ W3, __half* __restrict__ T3) {
    __shared__ float t[32][33];
    int bidx = blockIdx.x;
    int tid = threadIdx.x;
    if (bidx < NB_CONV) {
        int i = bidx * 256 + tid;
        float4 v = ((const float4*)rgb)[i];
        ((__half2*)Ah)[i * 2]     = __halves2half2(__float2half_rn(v.x), __float2half_rn(v.y));
        ((__half2*)Ah)[i * 2 + 1] = __halves2half2(__float2half_rn(v.z), __float2half_rn(v.w));
        return;
    }
    int tx = tid & 31, ty = tid >> 5;
    if (bidx < NB_CONV + NB_TRGB) {
        int lb = bidx - NB_CONV;          // (bx over 256, by over 16)
        int bx = lb & 255, by = lb >> 8;
        int k0 = bx * 32, n0 = by * 32;
        const float* src = (n0 < 256) ? vWr : qWr;
        int nb = (n0 < 256) ? n0 : (n0 - 256);
        #pragma unroll
        for (int i = 0; i < 4; i++)
            t[ty + i * 8][tx] = src[(size_t)(k0 + ty + i * 8) * 256 + nb + tx];
        __syncthreads();
        #pragma unroll
        for (int i = 0; i < 4; i++)
            Trgb[(size_t)(n0 + ty + i * 8) * REPRK + k0 + tx] = __float2half_rn(t[tx][ty + i * 8]);
        return;
    }
    int lb = bidx - NB_CONV - NB_TRGB;    // (bx 16, by 16, z 4)
    int bx = lb & 15, by = (lb >> 4) & 15, z = lb >> 8;
    const float* W = z == 0 ? W0 : z == 1 ? W1 : z == 2 ? W2 : W3;
    __half* T = z == 0 ? T0 : z == 1 ? T1 : z == 2 ? T2 : T3;
    int k0 = bx * 32, n0 = by * 32;
    #pragma unroll
    for (int i = 0; i < 4; i++)
        t[ty + i * 8][tx] = W[(size_t)(k0 + ty + i * 8) * 512 + n0 + tx];
    __syncthreads();
    #pragma unroll
    for (int i = 0; i < 4; i++)
        T[(size_t)(n0 + ty + i * 8) * 512 + k0 + tx] = __float2half_rn(t[tx][ty + i * 8]);
}

// ===================== merged features (ln_tanh_rgb + low), warp-per-row ====
// 768 threads = 24 warps. blocks [0,171): ln rows (4096 = b*2+hsel);
// [171,342): low rows (4096 = b*2+path).
#define NB_LNT 171
__global__ __launch_bounds__(768)
void feat_k(const float* __restrict__ part,
            const float* __restrict__ vg, const float* __restrict__ vb,
            const float* __restrict__ qg, const float* __restrict__ qb,
            const float* __restrict__ low,
            const float* __restrict__ vWl, const float* __restrict__ vgl, const float* __restrict__ vbl,
            const float* __restrict__ qWl, const float* __restrict__ qgl, const float* __restrict__ qbl,
            __half* __restrict__ xvh, __half* __restrict__ xqh) {
    const int lane = threadIdx.x & 31, w = threadIdx.x >> 5;
    const size_t np = (size_t)BB * 512;
    if (blockIdx.x < NB_LNT) {
        int gw = blockIdx.x * 24 + w;
        if (gw >= 4096) return;
        int b = gw >> 1, hsel = gw & 1;
        float x[8], s1 = 0.f, s2 = 0.f;
        #pragma unroll
        for (int i = 0; i < 8; i++) {
            size_t off = (size_t)b * 512 + hsel * 256 + lane + i * 32;
            x[i] = part[off] + part[off + np] + part[off + 2 * np] + part[off + 3 * np];
            s1 += x[i]; s2 += x[i] * x[i];
        }
        #pragma unroll
        for (int o = 16; o > 0; o >>= 1) {
            s1 += __shfl_xor_sync(0xffffffffu, s1, o);
            s2 += __shfl_xor_sync(0xffffffffu, s2, o);
        }
        float mu = s1 * (1.f / 256.f);
        float inv = rsqrtf(s2 * (1.f / 256.f) - mu * mu + 1e-5f);
        const float* g  = hsel ? qg : vg;
        const float* be = hsel ? qb : vb;
        __half* dst = hsel ? xqh : xvh;
        #pragma unroll
        for (int i = 0; i < 8; i++) {
            int col = lane + i * 32;
            dst[(size_t)b * 512 + col] = __float2half_rn(tanhf((x[i] - mu) * inv * g[col] + be[col]));
        }
    } else {
        int gw = (blockIdx.x - NB_LNT) * 24 + w;
        if (gw >= 4096) return;
        int b = gw >> 1, path = gw & 1;
        const float* W  = path ? qWl : vWl;
        const float* g  = path ? qgl : vgl;
        const float* be = path ? qbl : vbl;
        __half* dst = path ? xqh : xvh;
        float myv = low[b * 32 + lane];
        float sv[8];
        #pragma unroll
        for (int i = 0; i < 8; i++) sv[i] = 0.f;
        #pragma unroll
        for (int k = 0; k < 32; k++) {
            float lk = __shfl_sync(0xffffffffu, myv, k);
            #pragma unroll
            for (int i = 0; i < 8; i++)
                sv[i] += lk * W[k * 256 + lane + i * 32];
        }
        float s1 = 0.f, s2 = 0.f;
        #pragma unroll
        for (int i = 0; i < 8; i++) { s1 += sv[i]; s2 += sv[i] * sv[i]; }
        #pragma unroll
        for (int o = 16; o > 0; o >>= 1) {
            s1 += __shfl_xor_sync(0xffffffffu, s1, o);
            s2 += __shfl_xor_sync(0xffffffffu, s2, o);
        }
        float mu = s1 * (1.f / 256.f);
        float inv = rsqrtf(s2 * (1.f / 256.f) - mu * mu + 1e-5f);
        #pragma unroll
        for (int i = 0; i < 8; i++) {
            int col = lane + i * 32;
            dst[(size_t)b * 512 + 256 + col] =
                __float2half_rn(tanhf((sv[i] - mu) * inv * g[col] + be[col]));
        }
    }
}

// ===================== mid_k v2: warp-per-slot, no per-iter barriers ========
// 768 threads. blocks [0,2048): q1 (warp w = slot s); [2048, 2048+86): v ln_silu.
__global__ __launch_bounds__(768)
void mid_k(const float* __restrict__ qbp, const int* __restrict__ cat,
           const float* __restrict__ qW1, const float* __restrict__ qg1, const float* __restrict__ qb1,
           const float* __restrict__ t0p, const float* __restrict__ vg1, const float* __restrict__ vb1,
           __half* __restrict__ q1h, __half* __restrict__ t1h) {
    const size_t np = (size_t)BB * 512;
    const int lane = threadIdx.x & 31, w = threadIdx.x >> 5;
    if (blockIdx.x < BB) {
        __shared__ float wact[8 * 512];
        int b = blockIdx.x;
        for (int i = threadIdx.x; i < 8 * 512; i += 768)
            wact[i] = qW1[(size_t)(512 + (i >> 9)) * 512 + (i & 511)];
        // per-warp action coefficients (slot s = w), lanes 0..7 compute d
        int s = w;
        float myas = 0.f;
        if (lane < 8) {
            int ls = s >> 3, ds = s & 7;
            int lvl = ls + (lane < ds ? 1 : 0);
            float lowv = -1.f, width = 2.f, mid = 0.f;
            for (int l = 0; l < lvl; l++) {
                float wd = width * (1.f / 16.f);
                float c = (float)cat[(b * 3 + l) * 8 + lane];
                float nl = lowv + c * wd;
                mid = nl + 0.5f * wd;
                lowv = nl; width = wd;
            }
            myas = (lvl == 0) ? 0.f : mid;
        }
        float x[16];
        #pragma unroll
        for (int i = 0; i < 16; i++) {
            size_t off = (size_t)b * 512 + lane + i * 32;
            x[i] = qbp[off] + qbp[np + off];
        }
        __syncthreads();
        #pragma unroll
        for (int d = 0; d < 8; d++) {
            float av = __shfl_sync(0xffffffffu, myas, d);
            #pragma unroll
            for (int i = 0; i < 16; i++)
                x[i] += av * wact[d * 512 + lane + i * 32];
        }
        float s1 = 0.f, s2 = 0.f;
        #pragma unroll
        for (int i = 0; i < 16; i++) { s1 += x[i]; s2 += x[i] * x[i]; }
        #pragma unroll
        for (int o = 16; o > 0; o >>= 1) {
            s1 += __shfl_xor_sync(0xffffffffu, s1, o);
            s2 += __shfl_xor_sync(0xffffffffu, s2, o);
        }
        float mu = s1 * (1.f / 512.f);
        float inv = rsqrtf(s2 * (1.f / 512.f) - mu * mu + 1e-5f);
        size_t row = (size_t)s * BB + b;
        #pragma unroll
        for (int i = 0; i < 16; i++) {
            int col = lane + i * 32;
            q1h[row * 512 + col] =
                __float2half_rn(silu((x[i] - mu) * inv * qg1[col] + qb1[col]));
        }
    } else {
        int gw = (blockIdx.x - BB) * 24 + w;
        if (gw >= BB) return;
        size_t rowo = (size_t)gw * 512;
        float x[16], s1 = 0.f, s2 = 0.f;
        #pragma unroll
        for (int i = 0; i < 16; i++) {
            size_t off = rowo + lane + i * 32;
            x[i] = t0p[off] + t0p[np + off];
            s1 += x[i]; s2 += x[i] * x[i];
        }
        #pragma unroll
        for (int o = 16; o > 0; o >>= 1) {
            s1 += __shfl_xor_sync(0xffffffffu, s1, o);
            s2 += __shfl_xor_sync(0xffffffffu, s2, o);
        }
        float mu = s1 * (1.f / 512.f);
        float inv = rsqrtf(s2 * (1.f / 512.f) - mu * mu + 1e-5f);
        #pragma unroll
        for (int i = 0; i < 16; i++) {
            int col = lane + i * 32;
            t1h[rowo + col] =
                __float2half_rn(silu((x[i] - mu) * inv * vg1[col] + vb1[col]));
        }
    }
}

// vW2 partials -> LN -> SiLU -> value head, warp per b
__global__ __launch_bounds__(768)
void vfin(const float* __restrict__ t0p, const float* __restrict__ g,
          const float* __restrict__ be, const float* __restrict__ Wh,
          const float* __restrict__ bh, float* __restrict__ out) {
    const size_t np = (size_t)BB * 512;
    const int lane = threadIdx.x & 31, w = threadIdx.x >> 5;
    int b = blockIdx.x * 24 + w;
    if (b >= BB) return;
    float x[16], s1 = 0.f, s2 = 0.f;
    #pragma unroll
    for (int i = 0; i < 16; i++) {
        size_t off = (size_t)b * 512 + lane + i * 32;
        x[i] = t0p[off] + t0p[np + off];
        s1 += x[i]; s2 += x[i] * x[i];
    }
    #pragma unroll
    for (int o = 16; o > 0; o >>= 1) {
        s1 += __shfl_xor_sync(0xffffffffu, s1, o);
        s2 += __shfl_xor_sync(0xffffffffu, s2, o);
    }
    float mu = s1 * (1.f / 512.f);
    float inv = rsqrtf(s2 * (1.f / 512.f) - mu * mu + 1e-5f);
    float acc = 0.f;
    #pragma unroll
    for (int i = 0; i < 16; i++) {
        int col = lane + i * 32;
        acc += silu((x[i] - mu) * inv * g[col] + be[col]) * Wh[col];
    }
    #pragma unroll
    for (int o = 16; o > 0; o >>= 1)
        acc += __shfl_xor_sync(0xffffffffu, acc, o);
    if (lane == 0) out[b] = acc + bh[0];
}

// ---- fused LN + SiLU + HMMA diagonal q-head over q2pre (fp16, s-major) ----
#define LNW 520
__global__ __launch_bounds__(256)
void lnhead_q(const __half* __restrict__ pre, const float* __restrict__ g,
              const float* __restrict__ be, const float* __restrict__ Wh,
              const float* __restrict__ bh, float* __restrict__ out) {
    extern __shared__ __half smh[];
    __half* whsT = smh;              // [16][LNW]
    __half* ys   = smh + 16 * LNW;   // [64][LNW]
    const int tid = threadIdx.x, lane = tid & 31, w = tid >> 5;
    const int r0 = blockIdx.x * 64;
    const int s16 = (r0 >> 11) * 16;

    for (int i = tid; i < 16 * 512; i += 256) {
        int n = i & 15, k = i >> 4;
        whsT[n * LNW + k] = __float2half_rn(Wh[(size_t)k * SBH + s16 + n]);
    }

    for (int rr = w; rr < 64; rr += 8) {
        const __half2* row = (const __half2*)(pre + (size_t)(r0 + rr) * 512);
        float2 v[8];
        float s1 = 0.f, s2 = 0.f;
        #pragma unroll
        for (int i = 0; i < 8; i++) {
            v[i] = __half22float2(row[lane + i * 32]);
            s1 += v[i].x + v[i].y;
            s2 += v[i].x * v[i].x + v[i].y * v[i].y;
        }
        #pragma unroll
        for (int o = 16; o > 0; o >>= 1) {
            s1 += __shfl_xor_sync(0xffffffffu, s1, o);
            s2 += __shfl_xor_sync(0xffffffffu, s2, o);
        }
        float mu = s1 * (1.f / 512.f);
        float inv = rsqrtf(s2 * (1.f / 512.f) - mu * mu + 1e-5f);
        __half2* yr = (__half2*)(ys + rr * LNW);
        #pragma unroll
        for (int i = 0; i < 8; i++) {
            int col = 2 * (lane + i * 32);
            float2 gg = *(const float2*)&g[col];
            float2 bb = *(const float2*)&be[col];
            float y0 = silu((v[i].x - mu) * inv * gg.x + bb.x);
            float y1 = silu((v[i].y - mu) * inv * gg.y + bb.y);
            yr[lane + i * 32] = __floats2half2_rn(y0, y1);
        }
    }
    __syncthreads();

    if (w < 4) {
        const int mt = w;
        const int r15 = lane & 15, ks = lane >> 4;
        const uint32_t abase = smem_u32(ys)   + (uint32_t)((mt * 16 + r15) * (LNW * 2) + ks * 16);
        const uint32_t bbase = smem_u32(whsT) + (uint32_t)(r15 * (LNW * 2) + ks * 16);
        float acc[2][4] = {};
        #pragma unroll 4
        for (int kk = 0; kk < 32; kk++) {
            uint32_t a[4], b[4];
            ldsm4(a, abase + kk * 32);
            ldsm4(b, bbase + kk * 32);
            mma_f32acc(acc[0], a, b[0], b[2]);
            mma_f32acc(acc[1], a, b[1], b[3]);
        }
        int rloc = mt * 16 + (lane >> 2);
        int brow0 = (r0 + rloc) & (BB - 1);
        int brow1 = (r0 + rloc + 8) & (BB - 1);
        #pragma unroll
        for (int t = 0; t < 2; t++) {
            int col = t * 8 + (lane & 3) * 2;
            float2 bias = *(const float2*)&bh[s16 + col];
            *(float2*)&out[(size_t)brow0 * SBH + s16 + col] =
                make_float2(acc[t][0] + bias.x, acc[t][1] + bias.y);
            *(float2*)&out[(size_t)brow1 * SBH + s16 + col] =
                make_float2(acc[t][2] + bias.x, acc[t][3] + bias.y);
        }
    }
}

// ===================== launch ================================================
#define GEMM_DSMEM 65536
#define LNHEAD_DSMEM ((16 + 64) * LNW * 2)

extern "C" void kernel_launch(void* const* d_in, const int* in_sizes, int n_in,
                              void* d_out, int out_size) {
    const float* rgb_obs = (const float*)d_in[0];
    const float* low_obs = (const float*)d_in[1];
    const int*   category = (const int*)d_in[2];
    const float* v_W_rgb = (const float*)d_in[3];
    const float* v_g_rgb = (const float*)d_in[4];
    const float* v_b_rgb = (const float*)d_in[5];
    const float* v_W_low = (const float*)d_in[6];
    const float* v_g_low = (const float*)d_in[7];
    const float* v_b_low = (const float*)d_in[8];
    const float* v_W1 = (const float*)d_in[9];
    const float* v_g1 = (const float*)d_in[10];
    const float* v_b1 = (const float*)d_in[11];
    const float* v_W2 = (const float*)d_in[12];
    const float* v_g2 = (const float*)d_in[13];
    const float* v_b2 = (const float*)d_in[14];
    const float* v_Wh = (const float*)d_in[15];
    const float* v_bh = (const float*)d_in[16];
    const float* q_W_rgb = (const float*)d_in[17];
    const float* q_g_rgb = (const float*)d_in[18];
    const float* q_b_rgb = (const float*)d_in[19];
    const float* q_W_low = (const float*)d_in[20];
    const float* q_g_low = (const float*)d_in[21];
    const float* q_b_low = (const float*)d_in[22];
    const float* q_W1 = (const float*)d_in[23];
    const float* q_g1 = (const float*)d_in[24];
    const float* q_b1 = (const float*)d_in[25];
    const float* q_W2 = (const float*)d_in[26];
    const float* q_g2 = (const float*)d_in[27];
    const float* q_b2 = (const float*)d_in[28];
    const float* q_Wh = (const float*)d_in[29];
    const float* q_bh = (const float*)d_in[30];

    float* out_value = (float*)d_out;
    float* out_adv   = out_value + BB;

    cudaFuncSetAttribute(gemm_rgb,   cudaFuncAttributeMaxDynamicSharedMemorySize, GEMM_DSMEM);
    cudaFuncSetAttribute(gemm_dualA, cudaFuncAttributeMaxDynamicSharedMemorySize, GEMM_DSMEM);
    cudaFuncSetAttribute(gemm_dualB, cudaFuncAttributeMaxDynamicSharedMemorySize, GEMM_DSMEM);
    cudaFuncSetAttribute(lnhead_q,   cudaFuncAttributeMaxDynamicSharedMemorySize, LNHEAD_DSMEM);

    __half *Ahi, *WrgbT, *xvh, *xqh;
    __half *vW1T, *vW2T, *qW1T, *qW2T;
    __half *t1h, *q1h, *q2pre;
    float *rgb_part;
    cudaGetSymbolAddress((void**)&Ahi, g_Ahi);
    cudaGetSymbolAddress((void**)&WrgbT, g_WrgbTh);
    cudaGetSymbolAddress((void**)&rgb_part, g_rgb_part);
    cudaGetSymbolAddress((void**)&xvh, g_xvh);
    cudaGetSymbolAddress((void**)&xqh, g_xqh);
    cudaGetSymbolAddress((void**)&vW1T, g_vW1Th);
    cudaGetSymbolAddress((void**)&vW2T, g_vW2Th);
    cudaGetSymbolAddress((void**)&qW1T, g_qW1Th);
    cudaGetSymbolAddress((void**)&qW2T, g_qW2Th);
    cudaGetSymbolAddress((void**)&t1h, g_t1h);
    cudaGetSymbolAddress((void**)&q1h, g_q1h);
    cudaGetSymbolAddress((void**)&q2pre, g_q2pre);

    float* t0p = rgb_part;                        // slices 0,1
    float* qbp = rgb_part + 2 * (size_t)BB * 512; // slices 2,3

    // ---- prep (merged) ----
    prep_all<<<NB_CONV + NB_TRGB + 1024, 256>>>(rgb_obs, Ahi, v_W_rgb, q_W_rgb, WrgbT,
                                                v_W1, vW1T, v_W2, vW2T, q_W1, qW1T, q_W2, qW2T);

    // ---- shared rgb features ----
    gemm_rgb<<<dim3(4, BB / 128, 4), 256, GEMM_DSMEM>>>(Ahi, WrgbT, rgb_part);
    feat_k<<<2 * NB_LNT, 768>>>(rgb_part, v_g_rgb, v_b_rgb, q_g_rgb, q_b_rgb,
                                low_obs, v_W_low, v_g_low, v_b_low,
                                q_W_low, q_g_low, q_b_low, xvh, xqh);

    // ---- layer 1 ----
    gemm_dualA<<<dim3(4, 16, 4), 256, GEMM_DSMEM>>>(xvh, vW1T, xqh, qW1T, t0p, qbp);
    mid_k<<<BB + (BB + 23) / 24, 768>>>(qbp, category, q_W1, q_g1, q_b1,
                                        t0p, v_g1, v_b1, q1h, t1h);

    // ---- layer 2 ----
    gemm_dualB<<<dim3(4, 416), 256, GEMM_DSMEM>>>(q1h, qW2T, t1h, vW2T, q2pre, t0p);

    // ---- heads ----
    vfin<<<(BB + 23) / 24, 768>>>(t0p, v_g2, v_b2, v_Wh, v_bh, out_value);
    lnhead_q<<<(BB * SS) / 64, 256, LNHEAD_DSMEM>>>(q2pre, q_g2, q_b2, q_Wh, q_bh, out_adv);
}

// round 16
// speedup vs baseline: 2.1349x; 1.0539x over previous
#include <cuda_runtime.h>
#include <cuda_fp16.h>
#include <stdint.h>
#include <math.h>

#define BB    2048
#define REPRK 8192
#define SS    24
#define DD    8
#define SBH   384   // S*BINS

// ===================== PTX helpers (non-arch-specific) ======================
__device__ __forceinline__ uint32_t smem_u32(const void* p) {
    uint32_t a;
    asm("{ .reg .u64 t; cvta.to.shared.u64 t, %1; cvt.u32.u64 %0, t; }" : "=r"(a) : "l"(p));
    return a;
}
__device__ __forceinline__ void cp16(uint32_t saddr, const void* g) {
    asm volatile("cp.async.cg.shared.global [%0], [%1], 16;" :: "r"(saddr), "l"(g));
}
#define CPCOMMIT asm volatile("cp.async.commit_group;" ::: "memory")
#define CPWAIT2  asm volatile("cp.async.wait_group 2;" ::: "memory")

__device__ __forceinline__ void ldsm4(uint32_t* r, uint32_t addr) {
    asm volatile("ldmatrix.sync.aligned.m8n8.x4.shared.b16 {%0,%1,%2,%3}, [%4];"
        : "=r"(r[0]), "=r"(r[1]), "=r"(r[2]), "=r"(r[3]) : "r"(addr));
}
__device__ __forceinline__ void mma_f32acc(float* d, const uint32_t* a, uint32_t b0, uint32_t b1) {
    asm volatile("mma.sync.aligned.m16n8k16.row.col.f32.f16.f16.f32 "
        "{%0,%1,%2,%3}, {%4,%5,%6,%7}, {%8,%9}, {%0,%1,%2,%3};"
        : "+f"(d[0]), "+f"(d[1]), "+f"(d[2]), "+f"(d[3])
        : "r"(a[0]), "r"(a[1]), "r"(a[2]), "r"(a[3]), "r"(b0), "r"(b1));
}

// ===================== scratch (device globals) =============================
__device__ __half g_Ahi[(size_t)BB * REPRK];       // 32 MB
__device__ __half g_WrgbTh[(size_t)512 * REPRK];   // 8 MB
__device__ float g_rgb_part[2 * BB * 512];         // 8 MB: rgb splitk2, then t0/qb
__device__ __half g_xvh[BB * 512];
__device__ __half g_xqh[BB * 512];
__device__ __half g_vW1Th[512 * 512];
__device__ __half g_vW2Th[512 * 512];
__device__ __half g_qW1Th[512 * 512];
__device__ __half g_qW2Th[512 * 512];
__device__ __half g_t1h[BB * 512];
__device__ __half g_q1h[(size_t)BB * SS * 512];    // 50 MB (s-major rows)
__device__ __half g_q2pre[(size_t)BB * SS * 512];  // 50 MB (s-major rows, fp16)

// ===================== small helpers ========================================
__device__ __forceinline__ float silu(float z) { return z / (1.f + expf(-z)); }

// ===================== HMMA single-pass fp16 GEMM core (128x128 tile) =======
// 256 threads, 8 warps in 4x2 grid of 32x64 warp tiles. 4-stage ring.
template<bool HOUT>
__device__ __forceinline__ void gemm_core(
    const __half* __restrict__ A, const __half* __restrict__ B,
    void* __restrict__ Cv, int m0, int n0, int kbase, int lda, int N, int nch,
    char* smdyn) {
    const int tid = threadIdx.x;
    const int lane = tid & 31, wid = tid >> 5;
    const int wm = wid & 3, wn = wid >> 2;

    const int lrow = tid >> 2, lc = tid & 3;
    const int lpc = lc ^ ((lrow >> 1) & 3);
    const uint32_t sb0 = smem_u32(smdyn);
    const uint32_t s_store = sb0 + lrow * 64 + lpc * 16;
    const __half* gA = A + (size_t)(m0 + lrow) * lda + kbase + lc * 8;
    const __half* gB = B + (size_t)(n0 + lrow) * lda + kbase + lc * 8;
    const size_t l64 = (size_t)64 * lda;

#define LOADST(s, i) do { \
    uint32_t _so = s_store + (uint32_t)(s) * 16384u; \
    size_t _ko = (size_t)(i) * 32; \
    cp16(_so,               gA + _ko); \
    cp16(_so + 4096,        gA + l64 + _ko); \
    cp16(_so + 8192,        gB + _ko); \
    cp16(_so + 8192 + 4096, gB + l64 + _ko); } while (0)

    LOADST(0, 0); CPCOMMIT;
    LOADST(1, 1); CPCOMMIT;
    LOADST(2, 2); CPCOMMIT;

    float acc[2][8][4];
    #pragma unroll
    for (int mf = 0; mf < 2; mf++)
        #pragma unroll
        for (int nf = 0; nf < 8; nf++)
            #pragma unroll
            for (int r = 0; r < 4; r++) acc[mf][nf][r] = 0.f;

    const int r15 = lane & 15, ksel = lane >> 4;

    for (int i = 0; i < nch; i++) {
        CPWAIT2;
        __syncthreads();
        uint32_t sb = sb0 + (uint32_t)(i & 3) * 16384u;
        #pragma unroll
        for (int kt = 0; kt < 2; kt++) {
            const int cA = 2 * kt + ksel;
            uint32_t a[2][4], b[4][4];
            #pragma unroll
            for (int mf = 0; mf < 2; mf++) {
                int row = wm * 32 + mf * 16 + r15;
                uint32_t off = (uint32_t)(row * 64 + ((cA ^ ((row >> 1) & 3)) * 16));
                ldsm4(a[mf], sb + off);
            }
            #pragma unroll
            for (int nf4 = 0; nf4 < 4; nf4++) {
                int row = wn * 64 + nf4 * 16 + r15;
                uint32_t off = (uint32_t)(row * 64 + ((cA ^ ((row >> 1) & 3)) * 16));
                ldsm4(b[nf4], sb + 8192 + off);
            }
            #pragma unroll
            for (int mf = 0; mf < 2; mf++)
                #pragma unroll
                for (int nf4 = 0; nf4 < 4; nf4++) {
                    mma_f32acc(acc[mf][nf4 * 2],     a[mf], b[nf4][0], b[nf4][2]);
                    mma_f32acc(acc[mf][nf4 * 2 + 1], a[mf], b[nf4][1], b[nf4][3]);
                }
        }
        if (i + 3 < nch) LOADST((i + 3) & 3, i + 3);
        CPCOMMIT;
    }
#undef LOADST

    #pragma unroll
    for (int mf = 0; mf < 2; mf++)
        #pragma unroll
        for (int nf = 0; nf < 8; nf++) {
            int m = m0 + wm * 32 + mf * 16 + (lane >> 2);
            int n = n0 + wn * 64 + nf * 8 + (lane & 3) * 2;
            if (HOUT) {
                __half* Ch = (__half*)Cv;
                *(__half2*)&Ch[(size_t)m * N + n] = __floats2half2_rn(acc[mf][nf][0], acc[mf][nf][1]);
                *(__half2*)&Ch[(size_t)(m + 8) * N + n] = __floats2half2_rn(acc[mf][nf][2], acc[mf][nf][3]);
            } else {
                float* Cf = (float*)Cv;
                *(float2*)&Cf[(size_t)m * N + n] = make_float2(acc[mf][nf][0], acc[mf][nf][1]);
                *(float2*)&Cf[(size_t)(m + 8) * N + n] = make_float2(acc[mf][nf][2], acc[mf][nf][3]);
            }
        }
}

// rgb GEMM: grid (4, 16, 2) splitk2 over K=8192
__global__ __launch_bounds__(256, 2)
void gemm_rgb(const __half* __restrict__ A, const __half* __restrict__ B,
              float* __restrict__ C) {
    extern __shared__ char smdyn[];
    gemm_core<false>(A, B, C + (size_t)blockIdx.z * BB * 512,
                     blockIdx.y * 128, blockIdx.x * 128, blockIdx.z * 4096, REPRK, 512, 128, smdyn);
}

// vW1 + qW1 packed, full K each. grid (4, 16, 2): z = job
__global__ __launch_bounds__(256, 2)
void gemm_dualA(const __half* __restrict__ xvh, const __half* __restrict__ vB,
                const __half* __restrict__ xqh, const __half* __restrict__ qB,
                float* __restrict__ t0, float* __restrict__ qb) {
    extern __shared__ char smdyn[];
    int job = blockIdx.z;
    const __half* A = job ? xqh : xvh;
    const __half* B = job ? qB : vB;
    float* C = job ? qb : t0;
    gemm_core<false>(A, B, C, blockIdx.y * 128, blockIdx.x * 128, 0, 512, 512, 16, smdyn);
}

// qW2 (full, fp16 out) + vW2 (full K, f32 out). grid (4, 400)
__global__ __launch_bounds__(256, 2)
void gemm_dualB(const __half* __restrict__ q1h, const __half* __restrict__ qB,
                const __half* __restrict__ t1h, const __half* __restrict__ vB,
                __half* __restrict__ q2pre, float* __restrict__ t0) {
    extern __shared__ char smdyn[];
    int y = blockIdx.y;
    if (y < 384) {
        gemm_core<true>(q1h, qB, q2pre, y * 128, blockIdx.x * 128, 0, 512, 512, 16, smdyn);
    } else {
        gemm_core<false>(t1h, vB, t0, (y - 384) * 128, blockIdx.x * 128, 0, 512, 512, 16, smdyn);
    }
}

// ===================== merged prep (conv + both transposes) =================
// blocks [0,4096): conv (4x float4/thread); [4096,8192): trans_rgb; [8192,9216): trans4
#define NB_CONV 4096
#define NB_TRGB 4096
__global__ __launch_bounds__(256)
void prep_all(const float* __restrict__ rgb, __half* __restrict__ Ah,
              const float* __restrict__ vWr, const float* __restrict__ qWr, __half* __restrict__ Trgb,
              const float* __restrict__ W0, __half* __restrict__ T0,
              const float* __restrict__ W1, __half* __restrict__ T1,
              const float* __restrict__ W2, __half* __restrict__ T2,
              const float* __restrict__ W3, __half* __restrict__ T3) {
    __shared__ float t[32][33];
    int bidx = blockIdx.x;
    int tid = threadIdx.x;
    if (bidx < NB_CONV) {
        int i0 = bidx * 1024 + tid;
        #pragma unroll
        for (int j = 0; j < 4; j++) {
            int i = i0 + j * 256;
            float4 v = ((const float4*)rgb)[i];
            ((__half2*)Ah)[i * 2]     = __halves2half2(__float2half_rn(v.x), __float2half_rn(v.y));
            ((__half2*)Ah)[i * 2 + 1] = __halves2half2(__float2half_rn(v.z), __float2half_rn(v.w));
        }
        return;
    }
    int tx = tid & 31, ty = tid >> 5;
    if (bidx < NB_CONV + NB_TRGB) {
        int lb = bidx - NB_CONV;
        int bx = lb & 255, by = lb >> 8;
        int k0 = bx * 32, n0 = by * 32;
        const float* src = (n0 < 256) ? vWr : qWr;
        int nb = (n0 < 256) ? n0 : (n0 - 256);
        #pragma unroll
        for (int i = 0; i < 4; i++)
            t[ty + i * 8][tx] = src[(size_t)(k0 + ty + i * 8) * 256 + nb + tx];
        __syncthreads();
        #pragma unroll
        for (int i = 0; i < 4; i++)
            Trgb[(size_t)(n0 + ty + i * 8) * REPRK + k0 + tx] = __float2half_rn(t[tx][ty + i * 8]);
        return;
    }
    int lb = bidx - NB_CONV - NB_TRGB;
    int bx = lb & 15, by = (lb >> 4) & 15, z = lb >> 8;
    const float* W = z == 0 ? W0 : z == 1 ? W1 : z == 2 ? W2 : W3;
    __half* T = z == 0 ? T0 : z == 1 ? T1 : z == 2 ? T2 : T3;
    int k0 = bx * 32, n0 = by * 32;
    #pragma unroll
    for (int i = 0; i < 4; i++)
        t[ty + i * 8][tx] = W[(size_t)(k0 + ty + i * 8) * 512 + n0 + tx];
    __syncthreads();
    #pragma unroll
    for (int i = 0; i < 4; i++)
        T[(size_t)(n0 + ty + i * 8) * 512 + k0 + tx] = __float2half_rn(t[tx][ty + i * 8]);
}

// ===================== merged features (ln_tanh_rgb + low), warp-per-row ====
#define NB_LNT 171
__global__ __launch_bounds__(768)
void feat_k(const float* __restrict__ part,
            const float* __restrict__ vg, const float* __restrict__ vb,
            const float* __restrict__ qg, const float* __restrict__ qb,
            const float* __restrict__ low,
            const float* __restrict__ vWl, const float* __restrict__ vgl, const float* __restrict__ vbl,
            const float* __restrict__ qWl, const float* __restrict__ qgl, const float* __restrict__ qbl,
            __half* __restrict__ xvh, __half* __restrict__ xqh) {
    const int lane = threadIdx.x & 31, w = threadIdx.x >> 5;
    const size_t np = (size_t)BB * 512;
    if (blockIdx.x < NB_LNT) {
        int gw = blockIdx.x * 24 + w;
        if (gw >= 4096) return;
        int b = gw >> 1, hsel = gw & 1;
        float x[8], s1 = 0.f, s2 = 0.f;
        #pragma unroll
        for (int i = 0; i < 8; i++) {
            size_t off = (size_t)b * 512 + hsel * 256 + lane + i * 32;
            x[i] = part[off] + part[off + np];
            s1 += x[i]; s2 += x[i] * x[i];
        }
        #pragma unroll
        for (int o = 16; o > 0; o >>= 1) {
            s1 += __shfl_xor_sync(0xffffffffu, s1, o);
            s2 += __shfl_xor_sync(0xffffffffu, s2, o);
        }
        float mu = s1 * (1.f / 256.f);
        float inv = rsqrtf(s2 * (1.f / 256.f) - mu * mu + 1e-5f);
        const float* g  = hsel ? qg : vg;
        const float* be = hsel ? qb : vb;
        __half* dst = hsel ? xqh : xvh;
        #pragma unroll
        for (int i = 0; i < 8; i++) {
            int col = lane + i * 32;
            dst[(size_t)b * 512 + col] = __float2half_rn(tanhf((x[i] - mu) * inv * g[col] + be[col]));
        }
    } else {
        int gw = (blockIdx.x - NB_LNT) * 24 + w;
        if (gw >= 4096) return;
        int b = gw >> 1, path = gw & 1;
        const float* W  = path ? qWl : vWl;
        const float* g  = path ? qgl : vgl;
        const float* be = path ? qbl : vbl;
        __half* dst = path ? xqh : xvh;
        float myv = low[b * 32 + lane];
        float sv[8];
        #pragma unroll
        for (int i = 0; i < 8; i++) sv[i] = 0.f;
        #pragma unroll
        for (int k = 0; k < 32; k++) {
            float lk = __shfl_sync(0xffffffffu, myv, k);
            #pragma unroll
            for (int i = 0; i < 8; i++)
                sv[i] += lk * W[k * 256 + lane + i * 32];
        }
        float s1 = 0.f, s2 = 0.f;
        #pragma unroll
        for (int i = 0; i < 8; i++) { s1 += sv[i]; s2 += sv[i] * sv[i]; }
        #pragma unroll
        for (int o = 16; o > 0; o >>= 1) {
            s1 += __shfl_xor_sync(0xffffffffu, s1, o);
            s2 += __shfl_xor_sync(0xffffffffu, s2, o);
        }
        float mu = s1 * (1.f / 256.f);
        float inv = rsqrtf(s2 * (1.f / 256.f) - mu * mu + 1e-5f);
        #pragma unroll
        for (int i = 0; i < 8; i++) {
            int col = lane + i * 32;
            dst[(size_t)b * 512 + 256 + col] =
                __float2half_rn(tanhf((sv[i] - mu) * inv * g[col] + be[col]));
        }
    }
}

// ===================== mid_k: warp-per-slot =================================
// 768 threads. blocks [0,2048): q1 (warp w = slot s); rest: v ln_silu.
__global__ __launch_bounds__(768)
void mid_k(const float* __restrict__ qb, const int* __restrict__ cat,
           const float* __restrict__ qW1, const float* __restrict__ qg1, const float* __restrict__ qb1,
           const float* __restrict__ t0, const float* __restrict__ vg1, const float* __restrict__ vb1,
           __half* __restrict__ q1h, __half* __restrict__ t1h) {
    const int lane = threadIdx.x & 31, w = threadIdx.x >> 5;
    if (blockIdx.x < BB) {
        __shared__ float wact[8 * 512];
        int b = blockIdx.x;
        for (int i = threadIdx.x; i < 8 * 512; i += 768)
            wact[i] = qW1[(size_t)(512 + (i >> 9)) * 512 + (i & 511)];
        int s = w;
        float myas = 0.f;
        if (lane < 8) {
            int ls = s >> 3, ds = s & 7;
            int lvl = ls + (lane < ds ? 1 : 0);
            float lowv = -1.f, width = 2.f, mid = 0.f;
            for (int l = 0; l < lvl; l++) {
                float wd = width * (1.f / 16.f);
                float c = (float)cat[(b * 3 + l) * 8 + lane];
                float nl = lowv + c * wd;
                mid = nl + 0.5f * wd;
                lowv = nl; width = wd;
            }
            myas = (lvl == 0) ? 0.f : mid;
        }
        float x[16];
        #pragma unroll
        for (int i = 0; i < 16; i++)
            x[i] = qb[(size_t)b * 512 + lane + i * 32];
        __syncthreads();
        #pragma unroll
        for (int d = 0; d < 8; d++) {
            float av = __shfl_sync(0xffffffffu, myas, d);
            #pragma unroll
            for (int i = 0; i < 16; i++)
                x[i] += av * wact[d * 512 + lane + i * 32];
        }
        float s1 = 0.f, s2 = 0.f;
        #pragma unroll
        for (int i = 0; i < 16; i++) { s1 += x[i]; s2 += x[i] * x[i]; }
        #pragma unroll
        for (int o = 16; o > 0; o >>= 1) {
            s1 += __shfl_xor_sync(0xffffffffu, s1, o);
            s2 += __shfl_xor_sync(0xffffffffu, s2, o);
        }
        float mu = s1 * (1.f / 512.f);
        float inv = rsqrtf(s2 * (1.f / 512.f) - mu * mu + 1e-5f);
        size_t row = (size_t)s * BB + b;
        #pragma unroll
        for (int i = 0; i < 16; i++) {
            int col = lane + i * 32;
            q1h[row * 512 + col] =
                __float2half_rn(silu((x[i] - mu) * inv * qg1[col] + qb1[col]));
        }
    } else {
        int gw = (blockIdx.x - BB) * 24 + w;
        if (gw >= BB) return;
        size_t rowo = (size_t)gw * 512;
        float x[16], s1 = 0.f, s2 = 0.f;
        #pragma unroll
        for (int i = 0; i < 16; i++) {
            x[i] = t0[rowo + lane + i * 32];
            s1 += x[i]; s2 += x[i] * x[i];
        }
        #pragma unroll
        for (int o = 16; o > 0; o >>= 1) {
            s1 += __shfl_xor_sync(0xffffffffu, s1, o);
            s2 += __shfl_xor_sync(0xffffffffu, s2, o);
        }
        float mu = s1 * (1.f / 512.f);
        float inv = rsqrtf(s2 * (1.f / 512.f) - mu * mu + 1e-5f);
        #pragma unroll
        for (int i = 0; i < 16; i++) {
            int col = lane + i * 32;
            t1h[rowo + col] =
                __float2half_rn(silu((x[i] - mu) * inv * vg1[col] + vb1[col]));
        }
    }
}

// ---- fused LN + SiLU + HMMA diagonal q-head, plus value head (merged) -----
// blocks [0,768): q head over q2pre; blocks [768,1024): vfin (8 warps x b)
#define LNW 520
__global__ __launch_bounds__(256)
void lnhead_q(const __half* __restrict__ pre, const float* __restrict__ g,
              const float* __restrict__ be, const float* __restrict__ Wh,
              const float* __restrict__ bh, float* __restrict__ out,
              const float* __restrict__ t0, const float* __restrict__ vg2,
              const float* __restrict__ vb2, const float* __restrict__ vWh,
              const float* __restrict__ vbh, float* __restrict__ outv) {
    const int tid = threadIdx.x, lane = tid & 31, w = tid >> 5;
    if (blockIdx.x >= 768) {
        // ---- value head: warp per b ----
        int b = (blockIdx.x - 768) * 8 + w;
        float x[16], s1 = 0.f, s2 = 0.f;
        #pragma unroll
        for (int i = 0; i < 16; i++) {
            x[i] = t0[(size_t)b * 512 + lane + i * 32];
            s1 += x[i]; s2 += x[i] * x[i];
        }
        #pragma unroll
        for (int o = 16; o > 0; o >>= 1) {
            s1 += __shfl_xor_sync(0xffffffffu, s1, o);
            s2 += __shfl_xor_sync(0xffffffffu, s2, o);
        }
        float mu = s1 * (1.f / 512.f);
        float inv = rsqrtf(s2 * (1.f / 512.f) - mu * mu + 1e-5f);
        float acc = 0.f;
        #pragma unroll
        for (int i = 0; i < 16; i++) {
            int col = lane + i * 32;
            acc += silu((x[i] - mu) * inv * vg2[col] + vb2[col]) * vWh[col];
        }
        #pragma unroll
        for (int o = 16; o > 0; o >>= 1)
            acc += __shfl_xor_sync(0xffffffffu, acc, o);
        if (lane == 0) outv[b] = acc + vbh[0];
        return;
    }
    extern __shared__ __half smh[];
    __half* whsT = smh;              // [16][LNW]
    __half* ys   = smh + 16 * LNW;   // [64][LNW]
    const int r0 = blockIdx.x * 64;
    const int s16 = (r0 >> 11) * 16;

    for (int i = tid; i < 16 * 512; i += 256) {
        int n = i & 15, k = i >> 4;
        whsT[n * LNW + k] = __float2half_rn(Wh[(size_t)k * SBH + s16 + n]);
    }

    for (int rr = w; rr < 64; rr += 8) {
        const __half2* row = (const __half2*)(pre + (size_t)(r0 + rr) * 512);
        float2 v[8];
        float s1 = 0.f, s2 = 0.f;
        #pragma unroll
        for (int i = 0; i < 8; i++) {
            v[i] = __half22float2(row[lane + i * 32]);
            s1 += v[i].x + v[i].y;
            s2 += v[i].x * v[i].x + v[i].y * v[i].y;
        }
        #pragma unroll
        for (int o = 16; o > 0; o >>= 1) {
            s1 += __shfl_xor_sync(0xffffffffu, s1, o);
            s2 += __shfl_xor_sync(0xffffffffu, s2, o);
        }
        float mu = s1 * (1.f / 512.f);
        float inv = rsqrtf(s2 * (1.f / 512.f) - mu * mu + 1e-5f);
        __half2* yr = (__half2*)(ys + rr * LNW);
        #pragma unroll
        for (int i = 0; i < 8; i++) {
            int col = 2 * (lane + i * 32);
            float2 gg = *(const float2*)&g[col];
            float2 bb = *(const float2*)&be[col];
            float y0 = silu((v[i].x - mu) * inv * gg.x + bb.x);
            float y1 = silu((v[i].y - mu) * inv * gg.y + bb.y);
            yr[lane + i * 32] = __floats2half2_rn(y0, y1);
        }
    }
    __syncthreads();

    if (w < 4) {
        const int mt = w;
        const int r15 = lane & 15, ks = lane >> 4;
        const uint32_t abase = smem_u32(ys)   + (uint32_t)((mt * 16 + r15) * (LNW * 2) + ks * 16);
        const uint32_t bbase = smem_u32(whsT) + (uint32_t)(r15 * (LNW * 2) + ks * 16);
        float acc[2][4] = {};
        #pragma unroll 4
        for (int kk = 0; kk < 32; kk++) {
            uint32_t a[4], b[4];
            ldsm4(a, abase + kk * 32);
            ldsm4(b, bbase + kk * 32);
            mma_f32acc(acc[0], a, b[0], b[2]);
            mma_f32acc(acc[1], a, b[1], b[3]);
        }
        int rloc = mt * 16 + (lane >> 2);
        int brow0 = (r0 + rloc) & (BB - 1);
        int brow1 = (r0 + rloc + 8) & (BB - 1);
        #pragma unroll
        for (int t = 0; t < 2; t++) {
            int col = t * 8 + (lane & 3) * 2;
            float2 bias = *(const float2*)&bh[s16 + col];
            *(float2*)&out[(size_t)brow0 * SBH + s16 + col] =
                make_float2(acc[t][0] + bias.x, acc[t][1] + bias.y);
            *(float2*)&out[(size_t)brow1 * SBH + s16 + col] =
                make_float2(acc[t][2] + bias.x, acc[t][3] + bias.y);
        }
    }
}

// ===================== launch ================================================
#define GEMM_DSMEM 65536
#define LNHEAD_DSMEM ((16 + 64) * LNW * 2)

extern "C" void kernel_launch(void* const* d_in, const int* in_sizes, int n_in,
                              void* d_out, int out_size) {
    const float* rgb_obs = (const float*)d_in[0];
    const float* low_obs = (const float*)d_in[1];
    const int*   category = (const int*)d_in[2];
    const float* v_W_rgb = (const float*)d_in[3];
    const float* v_g_rgb = (const float*)d_in[4];
    const float* v_b_rgb = (const float*)d_in[5];
    const float* v_W_low = (const float*)d_in[6];
    const float* v_g_low = (const float*)d_in[7];
    const float* v_b_low = (const float*)d_in[8];
    const float* v_W1 = (const float*)d_in[9];
    const float* v_g1 = (const float*)d_in[10];
    const float* v_b1 = (const float*)d_in[11];
    const float* v_W2 = (const float*)d_in[12];
    const float* v_g2 = (const float*)d_in[13];
    const float* v_b2 = (const float*)d_in[14];
    const float* v_Wh = (const float*)d_in[15];
    const float* v_bh = (const float*)d_in[16];
    const float* q_W_rgb = (const float*)d_in[17];
    const float* q_g_rgb = (const float*)d_in[18];
    const float* q_b_rgb = (const float*)d_in[19];
    const float* q_W_low = (const float*)d_in[20];
    const float* q_g_low = (const float*)d_in[21];
    const float* q_b_low = (const float*)d_in[22];
    const float* q_W1 = (const float*)d_in[23];
    const float* q_g1 = (const float*)d_in[24];
    const float* q_b1 = (const float*)d_in[25];
    const float* q_W2 = (const float*)d_in[26];
    const float* q_g2 = (const float*)d_in[27];
    const float* q_b2 = (const float*)d_in[28];
    const float* q_Wh = (const float*)d_in[29];
    const float* q_bh = (const float*)d_in[30];

    float* out_value = (float*)d_out;
    float* out_adv   = out_value + BB;

    cudaFuncSetAttribute(gemm_rgb,   cudaFuncAttributeMaxDynamicSharedMemorySize, GEMM_DSMEM);
    cudaFuncSetAttribute(gemm_dualA, cudaFuncAttributeMaxDynamicSharedMemorySize, GEMM_DSMEM);
    cudaFuncSetAttribute(gemm_dualB, cudaFuncAttributeMaxDynamicSharedMemorySize, GEMM_DSMEM);
    cudaFuncSetAttribute(lnhead_q,   cudaFuncAttributeMaxDynamicSharedMemorySize, LNHEAD_DSMEM);

    __half *Ahi, *WrgbT, *xvh, *xqh;
    __half *vW1T, *vW2T, *qW1T, *qW2T;
    __half *t1h, *q1h, *q2pre;
    float *rgb_part;
    cudaGetSymbolAddress((void**)&Ahi, g_Ahi);
    cudaGetSymbolAddress((void**)&WrgbT, g_WrgbTh);
    cudaGetSymbolAddress((void**)&rgb_part, g_rgb_part);
    cudaGetSymbolAddress((void**)&xvh, g_xvh);
    cudaGetSymbolAddress((void**)&xqh, g_xqh);
    cudaGetSymbolAddress((void**)&vW1T, g_vW1Th);
    cudaGetSymbolAddress((void**)&vW2T, g_vW2Th);
    cudaGetSymbolAddress((void**)&qW1T, g_qW1Th);
    cudaGetSymbolAddress((void**)&qW2T, g_qW2Th);
    cudaGetSymbolAddress((void**)&t1h, g_t1h);
    cudaGetSymbolAddress((void**)&q1h, g_q1h);
    cudaGetSymbolAddress((void**)&q2pre, g_q2pre);

    float* t0 = rgb_part;                        // slice 0
    float* qb = rgb_part + (size_t)BB * 512;     // slice 1

    // ---- prep (merged) ----
    prep_all<<<NB_CONV + NB_TRGB + 1024, 256>>>(rgb_obs, Ahi, v_W_rgb, q_W_rgb, WrgbT,
                                                v_W1, vW1T, v_W2, vW2T, q_W1, qW1T, q_W2, qW2T);

    // ---- shared rgb features (splitk2, reduce folded into feat) ----
    gemm_rgb<<<dim3(4, BB / 128, 2), 256, GEMM_DSMEM>>>(Ahi, WrgbT, rgb_part);
    feat_k<<<2 * NB_LNT, 768>>>(rgb_part, v_g_rgb, v_b_rgb, q_g_rgb, q_b_rgb,
                                low_obs, v_W_low, v_g_low, v_b_low,
                                q_W_low, q_g_low, q_b_low, xvh, xqh);

    // ---- layer 1 (v + q packed, full K) ----
    gemm_dualA<<<dim3(4, 16, 2), 256, GEMM_DSMEM>>>(xvh, vW1T, xqh, qW1T, t0, qb);
    mid_k<<<BB + (BB + 23) / 24, 768>>>(qb, category, q_W1, q_g1, q_b1,
                                        t0, v_g1, v_b1, q1h, t1h);

    // ---- layer 2 ----
    gemm_dualB<<<dim3(4, 400), 256, GEMM_DSMEM>>>(q1h, qW2T, t1h, vW2T, q2pre, t0);

    // ---- heads (q head + value head in one launch) ----
    lnhead_q<<<1024, 256, LNHEAD_DSMEM>>>(q2pre, q_g2, q_b2, q_Wh, q_bh, out_adv,
                                          t0, v_g2, v_b2, v_Wh, v_bh, out_value);
}